// round 11
// baseline (speedup 1.0000x reference)
#include <cuda_runtime.h>
#include <cuda_fp16.h>
#include <cstdint>

#define NB 4
#define NS 4096
#define ND 64
#define SCALE2 0.18033688f   // 0.125 * log2(e): exp(x*0.125) = exp2(x*SCALE2)
#define STR 72u              // fp16 elems per smem row (144 B -> LDSM conflict-free)
#define TBYTES 9216u         // one 64x72 fp16 tile
#define BUFB 27648u          // one buffer group: KH + KL + VH

// dynamic smem: [Q 4608][2 x (KH, KL, VH)]; O-combine buffer reuses KV region
#define O_Q 0u
#define O_B 4608u
#define SMEM_SZ 59904u

// pre-split fp16 operand arrays (uint32 = fp16x2), rows of 128 B
__device__ __align__(128) uint32_t g_qh[(size_t)NB * NS * 32];  // fp16(q*SCALE2)
__device__ __align__(128) uint32_t g_kh[(size_t)NB * NS * 32];  // fp16 hi of kn
__device__ __align__(128) uint32_t g_kl[(size_t)NB * NS * 32];  // fp16 lo of kn
__device__ __align__(128) uint32_t g_vh[(size_t)NB * NS * 32];  // fp16(v)
__device__ float g_shift[NB * NS];

// ------------------------------------------------------------- PTX helpers
__device__ __forceinline__ uint32_t smem_u32(const void* p) {
    uint32_t a;
    asm("{ .reg .u64 t; cvta.to.shared.u64 t, %1; cvt.u32.u64 %0, t; }" : "=r"(a) : "l"(p));
    return a;
}
__device__ __forceinline__ uint64_t gaddr(const void* p) {
    uint64_t a;
    asm("cvta.to.global.u64 %0, %1;" : "=l"(a) : "l"(p));
    return a;
}
__device__ __forceinline__ void cp16(uint32_t dst, uint64_t src) {
    asm volatile("cp.async.cg.shared.global [%0], [%1], 16;" ::"r"(dst), "l"(src));
}
#define CP_COMMIT() asm volatile("cp.async.commit_group;" ::: "memory")
#define CP_WAIT1()  asm volatile("cp.async.wait_group 1;" ::: "memory")

__device__ __forceinline__ void ldsm4(uint32_t* d, uint32_t a) {
    asm volatile("ldmatrix.sync.aligned.m8n8.x4.shared.b16 {%0,%1,%2,%3}, [%4];"
                 : "=r"(d[0]), "=r"(d[1]), "=r"(d[2]), "=r"(d[3]) : "r"(a));
}
__device__ __forceinline__ void ldsm4t(uint32_t* d, uint32_t a) {
    asm volatile("ldmatrix.sync.aligned.m8n8.x4.trans.shared.b16 {%0,%1,%2,%3}, [%4];"
                 : "=r"(d[0]), "=r"(d[1]), "=r"(d[2]), "=r"(d[3]) : "r"(a));
}
__device__ __forceinline__ void mma_f16(float* c, const uint32_t* a, uint32_t b0, uint32_t b1) {
    asm volatile("mma.sync.aligned.m16n8k16.row.col.f32.f16.f16.f32 "
                 "{%0,%1,%2,%3}, {%4,%5,%6,%7}, {%8,%9}, {%0,%1,%2,%3};"
                 : "+f"(c[0]), "+f"(c[1]), "+f"(c[2]), "+f"(c[3])
                 : "r"(a[0]), "r"(a[1]), "r"(a[2]), "r"(a[3]), "r"(b0), "r"(b1));
}
__device__ __forceinline__ uint32_t h2u(__half2 h) { return *reinterpret_cast<uint32_t*>(&h); }
__device__ __forceinline__ void splith(float a, float b, uint32_t& hi, uint32_t& lo) {
    __half2 h = __floats2half2_rn(a, b);
    float2 f = __half22float2(h);
    __half2 l = __floats2half2_rn(a - f.x, b - f.y);
    hi = h2u(h);
    lo = h2u(l);
}

// ---------------------------------------------------------------------------
// Kernel 1: norms -> shift (log2-domain); fp16 Q*SCALE2, split Kn, fp16 V.
// ---------------------------------------------------------------------------
__global__ void prep_kernel(const float* __restrict__ qk, const float* __restrict__ v) {
    int row = blockIdx.x * 8 + (threadIdx.x >> 5);
    int lane = threadIdx.x & 31;
    float2 q = *(const float2*)(qk + (size_t)row * ND + lane * 2);
    float ss = q.x * q.x + q.y * q.y;
    #pragma unroll
    for (int o = 16; o >= 1; o >>= 1) ss += __shfl_xor_sync(0xffffffffu, ss, o);
    float nrm = fmaxf(sqrtf(ss), 1e-12f);
    float inv = 1.0f / nrm;
    size_t w = (size_t)row * 32 + lane;
    g_qh[w] = h2u(__floats2half2_rn(q.x * SCALE2, q.y * SCALE2));
    uint32_t hi, lo;
    splith(q.x * inv, q.y * inv, hi, lo);
    g_kh[w] = hi; g_kl[w] = lo;
    float2 vv = *(const float2*)(v + (size_t)row * ND + lane * 2);
    g_vh[w] = h2u(__floats2half2_rn(vv.x, vv.y));
    if (lane == 0) g_shift[row] = nrm * SCALE2;
}

// ---------------------------------------------------------------------------
// Kernel 2: fused attention, 32-row strips, 512 CTAs, 3 CTAs/SM.
// 8 warps = 2 row-groups(16) x 4 j-quarters(16). S 2-term, AV 1-term.
// In-CTA normalize sweep; 2-stage cp.async; log2-domain exp.
// ---------------------------------------------------------------------------
__global__ __launch_bounds__(256, 3)
void attn_main(const float* __restrict__ v,
               float* __restrict__ out, float* __restrict__ attn)
{
    extern __shared__ char smc[];
    const uint32_t sb = smem_u32(smc);
    const int tid = threadIdx.x, lane = tid & 31, w = tid >> 5;
    const int wy = w & 1, wx = w >> 1;   // row group (16 rows), j-quarter (16 cols)

    // 3-way balanced schedule over bid%148 SM slots; spill jobs are smallest
    int l = blockIdx.x;
    int s = l % 148, rnd = l / 148;
    int p;
    if (rnd == 0)      p = s;
    else if (rnd == 1) p = 295 - s;
    else if (rnd == 2) p = 443 - s;
    else               p = l;
    const int nt  = 64 - (p >> 3);                 // tiles for this strip
    const int r32 = 2 * (nt - 1) + ((p >> 2) & 1); // 32-row strip index
    const int b   = p & 3;
    const size_t bS = (size_t)b * NS;

    __shared__ float rspart[4][32];

    const uint64_t gqh = gaddr(g_qh);
    const uint64_t gkh = gaddr(g_kh), gkl = gaddr(g_kl);
    const uint64_t gvh = gaddr(g_vh);

    auto issue_kv = [&](int ct, uint32_t buf) {
        size_t t0 = (bS + (size_t)ct * 64) * 128;
        uint32_t kb = sb + O_B + buf * BUFB;
        #pragma unroll
        for (int c = 0; c < 2; ++c) {
            int idx = tid * 2 + c, r = idx >> 3, c8 = idx & 7;
            uint32_t so = (uint32_t)(r * 144 + c8 * 16);
            uint64_t go = t0 + (size_t)r * 128 + c8 * 16;
            cp16(kb + so, gkh + go);
            cp16(kb + TBYTES + so, gkl + go);
            cp16(kb + 2 * TBYTES + so, gvh + go);
        }
    };
    // prologue: G0 = Q(32 rows) + tile0; G1 = tile1 (or empty)
    {
        size_t q0 = (bS + (size_t)r32 * 32) * 128;
        int r = tid >> 3, c8 = tid & 7;   // exactly 256 16B chunks
        cp16(sb + O_Q + (uint32_t)(r * 144 + c8 * 16),
             gqh + q0 + (size_t)r * 128 + c8 * 16);
        issue_kv(0, 0);
        CP_COMMIT();
        if (nt > 1) issue_kv(1, 1);
        CP_COMMIT();
    }

    // ldmatrix byte-offset helpers (within a tile)
    const uint32_t A_off = (uint32_t)(((lane & 15) * STR + ((lane >> 4) << 3)) * 2);
    const uint32_t B_off = (uint32_t)(((((lane >> 4) << 3) + (lane & 7)) * STR + (((lane >> 3) & 1) << 3)) * 2);

    const int g = lane >> 2, t = lane & 3;
    const int r0 = wy * 16 + g;                    // 0..31 within strip
    const int gi0 = r32 * 32 + r0, gi1 = gi0 + 8;
    const float sh0 = g_shift[bS + gi0];
    const float sh1 = g_shift[bS + gi1];
    float* attn_b = attn + (size_t)b * NS * NS;
    float* arow0 = attn_b + (size_t)gi0 * NS;
    float* arow1 = attn_b + (size_t)gi1 * NS;

    float oc[8][4] = {};       // partial O[16 x 64] over this warp's j-quarter
    float rs0 = 0.f, rs1 = 0.f;

    for (int ct = 0; ct < nt; ++ct) {
        const uint32_t buf = (uint32_t)(ct & 1);
        CP_WAIT1();            // group for tile ct complete
        __syncthreads();

        // --- preload this warp's V fragments: rows j-quarter, 64 e-cols ---
        uint32_t vfr[4][4];
        const uint32_t vhb = sb + O_B + buf * BUFB + 2 * TBYTES
                           + (uint32_t)(wx * 16 * STR * 2);
        #pragma unroll
        for (int ep = 0; ep < 4; ++ep)
            ldsm4t(vfr[ep], vhb + A_off + (uint32_t)(ep * 32));

        // --- S[16x16] = Qs @ Kn^T (2-term) over this warp's j-quarter ---
        float sc[2][4] = {};
        const uint32_t khb = sb + O_B + buf * BUFB + (uint32_t)(wx * 16 * STR * 2);
        const uint32_t klb = khb + TBYTES;
        const uint32_t qo = sb + O_Q + A_off + (uint32_t)(wy * 16 * STR * 2);
        #pragma unroll
        for (int k = 0; k < 4; ++k) {
            uint32_t aq[4], bh[4], bl[4];
            uint32_t kcol = (uint32_t)(k * 32);
            ldsm4(aq, qo + kcol);
            ldsm4(bh, khb + B_off + kcol);
            ldsm4(bl, klb + B_off + kcol);
            mma_f16(sc[0], aq, bh[0], bh[1]);
            mma_f16(sc[0], aq, bl[0], bl[1]);
            mma_f16(sc[1], aq, bh[2], bh[3]);
            mma_f16(sc[1], aq, bl[2], bl[3]);
        }

        // --- exp2 + mask + unnormalized attn store + fp16 A-frag repack ---
        uint32_t ah_[4];
        const int gjb = ct * 64 + wx * 16 + 2 * t;
        #pragma unroll
        for (int nb = 0; nb < 2; ++nb) {
            int gj = gjb + nb * 8;
            float p00 = (gj < gi0)     ? exp2f(sc[nb][0] - sh0) : 0.f;
            float p01 = (gj + 1 < gi0) ? exp2f(sc[nb][1] - sh0) : 0.f;
            float p10 = (gj < gi1)     ? exp2f(sc[nb][2] - sh1) : 0.f;
            float p11 = (gj + 1 < gi1) ? exp2f(sc[nb][3] - sh1) : 0.f;
            rs0 += p00 + p01;
            rs1 += p10 + p11;
            *(float2*)(arow0 + gj) = make_float2(p00, p01);
            *(float2*)(arow1 + gj) = make_float2(p10, p11);
            ah_[2 * nb]     = h2u(__floats2half2_rn(p00, p01));
            ah_[2 * nb + 1] = h2u(__floats2half2_rn(p10, p11));
        }

        // --- O_partial += P @ V (8 MMAs, fragments preloaded) ---
        #pragma unroll
        for (int ep = 0; ep < 4; ++ep) {
            mma_f16(oc[2 * ep],     ah_, vfr[ep][0], vfr[ep][1]);
            mma_f16(oc[2 * ep + 1], ah_, vfr[ep][2], vfr[ep][3]);
        }

        __syncthreads();       // all warps done reading buf before overwrite
        if (ct + 2 < nt) issue_kv(ct + 2, buf);
        CP_COMMIT();
    }

    // ---- rowsum partial (this warp's 16 j-cols) -> smem ----
    rs0 += __shfl_xor_sync(0xffffffffu, rs0, 1);
    rs0 += __shfl_xor_sync(0xffffffffu, rs0, 2);
    rs1 += __shfl_xor_sync(0xffffffffu, rs1, 1);
    rs1 += __shfl_xor_sync(0xffffffffu, rs1, 2);
    if (t == 0) {
        rspart[wx][r0] = rs0;
        rspart[wx][r0 + 8] = rs1;
    }
    __syncthreads();   // rspart visible; all loop work done (KV region now free)

    // ---- combine j-quarter O partials via padded smem buffer ----
    float* obuf = (float*)(smc + O_B);   // [3][32][66] floats (reuse KV region)
    if (wx != 0) {
        float* ob = obuf + (size_t)(wx - 1) * 32 * 66;
        #pragma unroll
        for (int nb = 0; nb < 8; ++nb) {
            int c = nb * 8 + 2 * t;
            ob[r0 * 66 + c]           = oc[nb][0];
            ob[r0 * 66 + c + 1]       = oc[nb][1];
            ob[(r0 + 8) * 66 + c]     = oc[nb][2];
            ob[(r0 + 8) * 66 + c + 1] = oc[nb][3];
        }
    }
    __syncthreads();
    if (wx == 0) {
        float rt0 = rspart[0][r0] + rspart[1][r0] + rspart[2][r0] + rspart[3][r0];
        float rt1 = rspart[0][r0 + 8] + rspart[1][r0 + 8] + rspart[2][r0 + 8] + rspart[3][r0 + 8];
        float* o0 = out + (bS + gi0) * ND;
        float* o1 = out + (bS + gi1) * ND;
        if (gi0 == 0) {
            const float* vr = v + bS * ND;  // row 0: softmax over single -50000 diag
            #pragma unroll
            for (int nb = 0; nb < 8; ++nb) {
                int c = nb * 8 + 2 * t;
                *(float2*)(o0 + c) = *(const float2*)(vr + c);
            }
        } else {
            float i0 = 1.0f / rt0;
            #pragma unroll
            for (int nb = 0; nb < 8; ++nb) {
                int c = nb * 8 + 2 * t;
                float s0 = oc[nb][0] + obuf[r0 * 66 + c] + obuf[(32 + r0) * 66 + c]
                         + obuf[(64 + r0) * 66 + c];
                float s1 = oc[nb][1] + obuf[r0 * 66 + c + 1] + obuf[(32 + r0) * 66 + c + 1]
                         + obuf[(64 + r0) * 66 + c + 1];
                *(float2*)(o0 + c) = make_float2(s0 * i0, s1 * i0);
            }
        }
        float i1 = 1.0f / rt1;
        #pragma unroll
        for (int nb = 0; nb < 8; ++nb) {
            int c = nb * 8 + 2 * t;
            float s0 = oc[nb][2] + obuf[(r0 + 8) * 66 + c] + obuf[(40 + r0) * 66 + c]
                     + obuf[(72 + r0) * 66 + c];
            float s1 = oc[nb][3] + obuf[(r0 + 8) * 66 + c + 1] + obuf[(40 + r0) * 66 + c + 1]
                     + obuf[(72 + r0) * 66 + c + 1];
            *(float2*)(o1 + c) = make_float2(s0 * i1, s1 * i1);
        }
    }

    // ---- in-CTA normalize sweep (lower) + zero-fill (upper), 8 thr/row ----
    {
        int r = tid >> 3;
        float rs = rspart[0][r] + rspart[1][r] + rspart[2][r] + rspart[3][r];
        float inv = rs > 0.f ? 1.0f / rs : 0.f;
        float* rowp = attn_b + (size_t)(r32 * 32 + r) * NS;
        const int cl = nt * 64;
        for (int c = (tid & 7) * 4; c < cl; c += 32) {
            float4 a = *(float4*)(rowp + c);
            a.x *= inv; a.y *= inv; a.z *= inv; a.w *= inv;
            *(float4*)(rowp + c) = a;
        }
        float4 z = make_float4(0.f, 0.f, 0.f, 0.f);
        for (int c = cl + (tid & 7) * 4; c < NS; c += 32)
            *(float4*)(rowp + c) = z;
    }
    if (r32 == 0 && tid == 0) attn_b[0] = 1.0f;  // row 0: softmax over single diag entry
}

// ---------------------------------------------------------------------------
extern "C" void kernel_launch(void* const* d_in, const int* in_sizes, int n_in,
                              void* d_out, int out_size) {
    const float* qk = (const float*)d_in[0];
    const float* v  = (const float*)d_in[1];
    float* out  = (float*)d_out;
    float* attn = out + (size_t)NB * NS * ND;

    cudaFuncSetAttribute(attn_main, cudaFuncAttributeMaxDynamicSharedMemorySize, SMEM_SZ);
    prep_kernel<<<NB * NS / 8, 256>>>(qk, v);
    attn_main<<<512, 256, SMEM_SZ>>>(v, out, attn);
}

// round 12
// speedup vs baseline: 1.0356x; 1.0356x over previous
#include <cuda_runtime.h>
#include <cuda_fp16.h>
#include <cstdint>

#define NB 4
#define NS 4096
#define ND 64
#define SCALE2 0.18033688f   // 0.125 * log2(e): exp(x*0.125) = exp2(x*SCALE2)
#define STR 72u              // fp16 elems per smem row (144 B -> LDSM conflict-free)
#define TBYTES 9216u         // one 64x72 fp16 tile
#define BUFB 27648u          // one buffer group: KH + KL + VH

// dynamic smem: [Q 9216][P-stage 17408][2 x (KH, KL, VH)]
#define O_Q  0u
#define O_ST 9216u
#define O_B  26624u
#define SMEM_SZ 81920u

// pre-split fp16 operand arrays (uint32 = fp16x2), rows of 128 B
__device__ __align__(128) uint32_t g_qh[(size_t)NB * NS * 32];  // fp16(q*SCALE2)
__device__ __align__(128) uint32_t g_kh[(size_t)NB * NS * 32];  // fp16 hi of kn
__device__ __align__(128) uint32_t g_kl[(size_t)NB * NS * 32];  // fp16 lo of kn
__device__ __align__(128) uint32_t g_vh[(size_t)NB * NS * 32];  // fp16(v)
__device__ float g_shift[NB * NS];

// ------------------------------------------------------------- PTX helpers
__device__ __forceinline__ uint32_t smem_u32(const void* p) {
    uint32_t a;
    asm("{ .reg .u64 t; cvta.to.shared.u64 t, %1; cvt.u32.u64 %0, t; }" : "=r"(a) : "l"(p));
    return a;
}
__device__ __forceinline__ uint64_t gaddr(const void* p) {
    uint64_t a;
    asm("cvta.to.global.u64 %0, %1;" : "=l"(a) : "l"(p));
    return a;
}
__device__ __forceinline__ void cp16(uint32_t dst, uint64_t src) {
    asm volatile("cp.async.cg.shared.global [%0], [%1], 16;" ::"r"(dst), "l"(src));
}
#define CP_COMMIT() asm volatile("cp.async.commit_group;" ::: "memory")
#define CP_WAIT1()  asm volatile("cp.async.wait_group 1;" ::: "memory")

__device__ __forceinline__ void ldsm4(uint32_t* d, uint32_t a) {
    asm volatile("ldmatrix.sync.aligned.m8n8.x4.shared.b16 {%0,%1,%2,%3}, [%4];"
                 : "=r"(d[0]), "=r"(d[1]), "=r"(d[2]), "=r"(d[3]) : "r"(a));
}
__device__ __forceinline__ void ldsm4t(uint32_t* d, uint32_t a) {
    asm volatile("ldmatrix.sync.aligned.m8n8.x4.trans.shared.b16 {%0,%1,%2,%3}, [%4];"
                 : "=r"(d[0]), "=r"(d[1]), "=r"(d[2]), "=r"(d[3]) : "r"(a));
}
__device__ __forceinline__ void mma_f16(float* c, const uint32_t* a, uint32_t b0, uint32_t b1) {
    asm volatile("mma.sync.aligned.m16n8k16.row.col.f32.f16.f16.f32 "
                 "{%0,%1,%2,%3}, {%4,%5,%6,%7}, {%8,%9}, {%0,%1,%2,%3};"
                 : "+f"(c[0]), "+f"(c[1]), "+f"(c[2]), "+f"(c[3])
                 : "r"(a[0]), "r"(a[1]), "r"(a[2]), "r"(a[3]), "r"(b0), "r"(b1));
}
__device__ __forceinline__ uint32_t h2u(__half2 h) { return *reinterpret_cast<uint32_t*>(&h); }
__device__ __forceinline__ void splith(float a, float b, uint32_t& hi, uint32_t& lo) {
    __half2 h = __floats2half2_rn(a, b);
    float2 f = __half22float2(h);
    __half2 l = __floats2half2_rn(a - f.x, b - f.y);
    hi = h2u(h);
    lo = h2u(l);
}

// ---------------------------------------------------------------------------
// Kernel 1: norms -> shift (log2-domain); fp16 Q*SCALE2, split Kn, fp16 V.
// ---------------------------------------------------------------------------
__global__ void prep_kernel(const float* __restrict__ qk, const float* __restrict__ v) {
    int row = blockIdx.x * 8 + (threadIdx.x >> 5);
    int lane = threadIdx.x & 31;
    float2 q = *(const float2*)(qk + (size_t)row * ND + lane * 2);
    float ss = q.x * q.x + q.y * q.y;
    #pragma unroll
    for (int o = 16; o >= 1; o >>= 1) ss += __shfl_xor_sync(0xffffffffu, ss, o);
    float nrm = fmaxf(sqrtf(ss), 1e-12f);
    float inv = 1.0f / nrm;
    size_t w = (size_t)row * 32 + lane;
    g_qh[w] = h2u(__floats2half2_rn(q.x * SCALE2, q.y * SCALE2));
    uint32_t hi, lo;
    splith(q.x * inv, q.y * inv, hi, lo);
    g_kh[w] = hi; g_kl[w] = lo;
    float2 vv = *(const float2*)(v + (size_t)row * ND + lane * 2);
    g_vh[w] = h2u(__floats2half2_rn(vv.x, vv.y));
    if (lane == 0) g_shift[row] = nrm * SCALE2;
}

// ---------------------------------------------------------------------------
// Kernel 2: fused attention, 64-row strips, 256 CTAs (R10 shape).
// Q fragments register-resident; p staged in smem -> coalesced STG.128;
// 2-stage cp.async; in-CTA normalize sweep; log2-domain exp.
// ---------------------------------------------------------------------------
__global__ __launch_bounds__(256, 2)
void attn_main(const float* __restrict__ v,
               float* __restrict__ out, float* __restrict__ attn)
{
    extern __shared__ char smc[];
    const uint32_t sb = smem_u32(smc);
    const int tid = threadIdx.x, lane = tid & 31, w = tid >> 5;
    const int wy = w & 3, wx = w >> 2;   // row group (16 rows), col half (32 j-cols)

    // balanced schedule: paired SMs sum to 65 tile-iters
    int l = blockIdx.x, rt, b;
    if (l < 40)       { rt = 63 - (l >> 2); b = l & 3; }
    else if (l < 148) { int i = l - 40; rt = 53 - (i >> 2); b = i & 3; }
    else              { int i = l - 148; rt = i >> 2; b = i & 3; }
    const size_t bS = (size_t)b * NS;
    const int nt = rt + 1;

    __shared__ float rspart[2][64];

    const uint64_t gqh = gaddr(g_qh);
    const uint64_t gkh = gaddr(g_kh), gkl = gaddr(g_kl);
    const uint64_t gvh = gaddr(g_vh);

    auto issue_kv = [&](int ct, uint32_t buf) {
        size_t t0 = (bS + (size_t)ct * 64) * 128;
        uint32_t kb = sb + O_B + buf * BUFB;
        #pragma unroll
        for (int c = 0; c < 2; ++c) {
            int idx = tid * 2 + c, r = idx >> 3, c8 = idx & 7;
            uint32_t so = (uint32_t)(r * 144 + c8 * 16);
            uint64_t go = t0 + (size_t)r * 128 + c8 * 16;
            cp16(kb + so, gkh + go);
            cp16(kb + TBYTES + so, gkl + go);
            cp16(kb + 2 * TBYTES + so, gvh + go);
        }
    };

    // ldmatrix byte-offset helpers (within a tile)
    const uint32_t A_off = (uint32_t)(((lane & 15) * STR + ((lane >> 4) << 3)) * 2);
    const uint32_t B_off = (uint32_t)(((((lane >> 4) << 3) + (lane & 7)) * STR + (((lane >> 3) & 1) << 3)) * 2);

    // prologue: G0 = Q(64 rows)+tile0; G1 = tile1 (or empty)
    {
        size_t q0 = (bS + (size_t)rt * 64) * 128;
        #pragma unroll
        for (int c = 0; c < 2; ++c) {
            int idx = tid * 2 + c, r = idx >> 3, c8 = idx & 7;
            cp16(sb + O_Q + (uint32_t)(r * 144 + c8 * 16),
                 gqh + q0 + (size_t)r * 128 + c8 * 16);
        }
        issue_kv(0, 0);
        CP_COMMIT();
        if (nt > 1) issue_kv(1, 1);
        CP_COMMIT();
    }
    CP_WAIT1();          // Q + tile0 ready
    __syncthreads();

    // --- Q fragments -> registers (loop-invariant) ---
    uint32_t aqf[4][4];
    {
        const uint32_t qo = sb + O_Q + A_off + (uint32_t)(wy * 16 * STR * 2);
        #pragma unroll
        for (int k = 0; k < 4; ++k) ldsm4(aqf[k], qo + (uint32_t)(k * 32));
    }

    const int g = lane >> 2, t = lane & 3;
    const int r0 = wy * 16 + g;
    const int gi0 = rt * 64 + r0, gi1 = gi0 + 8;
    const float sh0 = g_shift[bS + gi0];
    const float sh1 = g_shift[bS + gi1];
    float* attn_b = attn + (size_t)b * NS * NS;
    float* stage = (float*)(smc + O_ST);   // 64 x 68 fp32

    float oc[8][4] = {};       // partial O[16 x 64] over this warp's j-half
    float rs0 = 0.f, rs1 = 0.f;

    for (int ct = 0; ct < nt; ++ct) {
        const uint32_t buf = (uint32_t)(ct & 1);
        if (ct > 0) { CP_WAIT1(); __syncthreads(); }   // tile ct ready; stage free

        // --- preload V fragments kb=0 (overlaps S compute) ---
        uint32_t vfr0[4][4], vfr1[4][4];
        const uint32_t vhb = sb + O_B + buf * BUFB + 2 * TBYTES
                           + (uint32_t)(wx * 32 * STR * 2);
        #pragma unroll
        for (int ep = 0; ep < 4; ++ep)
            ldsm4t(vfr0[ep], vhb + A_off + (uint32_t)(ep * 32));

        // --- S[16x32] = Qs @ Kn^T (2-term, Q from registers) ---
        float sc[4][4] = {};
        const uint32_t khb = sb + O_B + buf * BUFB + (uint32_t)(wx * 32 * STR * 2);
        const uint32_t klb = khb + TBYTES;
        #pragma unroll
        for (int k = 0; k < 4; ++k) {
            uint32_t bh[4], bl[4];
            uint32_t kcol = (uint32_t)(k * 32);
            #pragma unroll
            for (int np = 0; np < 2; ++np) {
                uint32_t jo = (uint32_t)(np * 16 * STR * 2);
                ldsm4(bh, khb + B_off + jo + kcol);
                ldsm4(bl, klb + B_off + jo + kcol);
                mma_f16(sc[2 * np],     aqf[k], bh[0], bh[1]);
                mma_f16(sc[2 * np],     aqf[k], bl[0], bl[1]);
                mma_f16(sc[2 * np + 1], aqf[k], bh[2], bh[3]);
                mma_f16(sc[2 * np + 1], aqf[k], bl[2], bl[3]);
            }
        }
        // V fragments kb=1
        #pragma unroll
        for (int ep = 0; ep < 4; ++ep)
            ldsm4t(vfr1[ep], vhb + A_off + (uint32_t)(16 * STR * 2) + (uint32_t)(ep * 32));

        // --- exp2 + mask + p -> smem stage + fp16 A-frag repack ---
        uint32_t ah_[2][4];
        const int gjb = ct * 64 + wx * 32 + 2 * t;
        const int cjb = wx * 32 + 2 * t;
        #pragma unroll
        for (int nb = 0; nb < 4; ++nb) {
            int gj = gjb + nb * 8;
            float p00 = (gj < gi0)     ? exp2f(sc[nb][0] - sh0) : 0.f;
            float p01 = (gj + 1 < gi0) ? exp2f(sc[nb][1] - sh0) : 0.f;
            float p10 = (gj < gi1)     ? exp2f(sc[nb][2] - sh1) : 0.f;
            float p11 = (gj + 1 < gi1) ? exp2f(sc[nb][3] - sh1) : 0.f;
            rs0 += p00 + p01;
            rs1 += p10 + p11;
            int cj = cjb + nb * 8;
            *(float2*)(stage + r0 * 68 + cj)       = make_float2(p00, p01);
            *(float2*)(stage + (r0 + 8) * 68 + cj) = make_float2(p10, p11);
            int kb = nb >> 1, o = (nb & 1) * 2;
            ah_[kb][o]     = h2u(__floats2half2_rn(p00, p01));
            ah_[kb][o + 1] = h2u(__floats2half2_rn(p10, p11));
        }

        // --- O_partial += P @ V (pure MMA burst) ---
        #pragma unroll
        for (int ep = 0; ep < 4; ++ep) {
            mma_f16(oc[2 * ep],     ah_[0], vfr0[ep][0], vfr0[ep][1]);
            mma_f16(oc[2 * ep + 1], ah_[0], vfr0[ep][2], vfr0[ep][3]);
            mma_f16(oc[2 * ep],     ah_[1], vfr1[ep][0], vfr1[ep][1]);
            mma_f16(oc[2 * ep + 1], ah_[1], vfr1[ep][2], vfr1[ep][3]);
        }

        __syncthreads();   // stage complete; KV buf reads done

        // --- coalesced tile writeback: 64 rows x 256 B, STG.128 ---
        {
            int r = tid >> 2, q = tid & 3;
            const float* srow = stage + r * 68 + q * 16;
            float* drow = attn_b + (size_t)(rt * 64 + r) * NS + ct * 64 + q * 16;
            #pragma unroll
            for (int i = 0; i < 4; ++i)
                *(float4*)(drow + 4 * i) = *(const float4*)(srow + 4 * i);
        }
        if (ct + 2 < nt) { issue_kv(ct + 2, buf); CP_COMMIT(); }
    }

    // ---- rowsum partial (this warp's 32 j-cols) -> smem ----
    rs0 += __shfl_xor_sync(0xffffffffu, rs0, 1);
    rs0 += __shfl_xor_sync(0xffffffffu, rs0, 2);
    rs1 += __shfl_xor_sync(0xffffffffu, rs1, 1);
    rs1 += __shfl_xor_sync(0xffffffffu, rs1, 2);
    if (t == 0) {
        rspart[wx][r0] = rs0;
        rspart[wx][r0 + 8] = rs1;
    }
    __syncthreads();   // rspart visible; stage LDS done (stage reusable as obuf)

    // ---- combine column-half O partials via padded smem buffer ----
    float* obuf = stage;   // 64 x 66 floats
    if (wx == 1) {
        #pragma unroll
        for (int nb = 0; nb < 8; ++nb) {
            int c = nb * 8 + 2 * t;
            obuf[r0 * 66 + c]           = oc[nb][0];
            obuf[r0 * 66 + c + 1]       = oc[nb][1];
            obuf[(r0 + 8) * 66 + c]     = oc[nb][2];
            obuf[(r0 + 8) * 66 + c + 1] = oc[nb][3];
        }
    }
    __syncthreads();
    if (wx == 0) {
        float rt0 = rspart[0][r0] + rspart[1][r0];
        float rt1 = rspart[0][r0 + 8] + rspart[1][r0 + 8];
        float* o0 = out + (bS + gi0) * ND;
        float* o1 = out + (bS + gi1) * ND;
        if (gi0 == 0) {
            const float* vr = v + bS * ND;  // row 0: softmax over single -50000 diag
            #pragma unroll
            for (int nb = 0; nb < 8; ++nb) {
                int c = nb * 8 + 2 * t;
                *(float2*)(o0 + c) = *(const float2*)(vr + c);
            }
        } else {
            float i0 = 1.0f / rt0;
            #pragma unroll
            for (int nb = 0; nb < 8; ++nb) {
                int c = nb * 8 + 2 * t;
                *(float2*)(o0 + c) = make_float2((oc[nb][0] + obuf[r0 * 66 + c]) * i0,
                                                 (oc[nb][1] + obuf[r0 * 66 + c + 1]) * i0);
            }
        }
        float i1 = 1.0f / rt1;
        #pragma unroll
        for (int nb = 0; nb < 8; ++nb) {
            int c = nb * 8 + 2 * t;
            *(float2*)(o1 + c) = make_float2((oc[nb][2] + obuf[(r0 + 8) * 66 + c]) * i1,
                                             (oc[nb][3] + obuf[(r0 + 8) * 66 + c + 1]) * i1);
        }
    }

    // ---- in-CTA normalize sweep (lower) + zero-fill (upper), 4 thr/row ----
    {
        int r = tid >> 2;
        float rs = rspart[0][r] + rspart[1][r];
        float inv = rs > 0.f ? 1.0f / rs : 0.f;
        float* rowp = attn_b + (size_t)(rt * 64 + r) * NS;
        const int cl = nt * 64;
        for (int c = (tid & 3) * 4; c < cl; c += 16) {
            float4 a = *(float4*)(rowp + c);
            a.x *= inv; a.y *= inv; a.z *= inv; a.w *= inv;
            *(float4*)(rowp + c) = a;
        }
        float4 z = make_float4(0.f, 0.f, 0.f, 0.f);
        for (int c = cl + (tid & 3) * 4; c < NS; c += 16)
            *(float4*)(rowp + c) = z;
    }
    if (rt == 0 && tid == 0) attn_b[0] = 1.0f;  // row 0: softmax over single diag entry
}

// ---------------------------------------------------------------------------
extern "C" void kernel_launch(void* const* d_in, const int* in_sizes, int n_in,
                              void* d_out, int out_size) {
    const float* qk = (const float*)d_in[0];
    const float* v  = (const float*)d_in[1];
    float* out  = (float*)d_out;
    float* attn = out + (size_t)NB * NS * ND;

    cudaFuncSetAttribute(attn_main, cudaFuncAttributeMaxDynamicSharedMemorySize, SMEM_SZ);
    prep_kernel<<<NB * NS / 8, 256>>>(qk, v);
    attn_main<<<256, 256, SMEM_SZ>>>(v, out, attn);
}

// round 13
// speedup vs baseline: 1.0713x; 1.0345x over previous
#include <cuda_runtime.h>
#include <cuda_fp16.h>
#include <cstdint>

#define NB 4
#define NS 4096
#define ND 64
#define SCALE2 0.18033688f   // 0.125 * log2(e): exp(x*0.125) = exp2(x*SCALE2)
#define STR 72u              // fp16 elems per smem row (144 B -> LDSM conflict-free)
#define TBYTES 9216u         // one 64x72 fp16 tile
#define BUFB 27648u          // one buffer group: KH + KL + VH

// dynamic smem: [Q 9216][3 x (KH, KL, VH)]; O-combine buffer reuses KV region
#define O_Q 0u
#define O_B 9216u
#define SMEM_SZ 92160u

// pre-split fp16 operand arrays (uint32 = fp16x2), rows of 128 B
__device__ __align__(128) uint32_t g_qh[(size_t)NB * NS * 32];  // fp16(q*SCALE2)
__device__ __align__(128) uint32_t g_kh[(size_t)NB * NS * 32];  // fp16 hi of kn
__device__ __align__(128) uint32_t g_kl[(size_t)NB * NS * 32];  // fp16 lo of kn
__device__ __align__(128) uint32_t g_vh[(size_t)NB * NS * 32];  // fp16(v)
__device__ float g_shift[NB * NS];

// ------------------------------------------------------------- PTX helpers
__device__ __forceinline__ uint32_t smem_u32(const void* p) {
    uint32_t a;
    asm("{ .reg .u64 t; cvta.to.shared.u64 t, %1; cvt.u32.u64 %0, t; }" : "=r"(a) : "l"(p));
    return a;
}
__device__ __forceinline__ uint64_t gaddr(const void* p) {
    uint64_t a;
    asm("cvta.to.global.u64 %0, %1;" : "=l"(a) : "l"(p));
    return a;
}
__device__ __forceinline__ void cp16(uint32_t dst, uint64_t src) {
    asm volatile("cp.async.cg.shared.global [%0], [%1], 16;" ::"r"(dst), "l"(src));
}
#define CP_COMMIT() asm volatile("cp.async.commit_group;" ::: "memory")
#define CP_WAIT1()  asm volatile("cp.async.wait_group 1;" ::: "memory")
#define CP_WAIT0()  asm volatile("cp.async.wait_group 0;" ::: "memory")

__device__ __forceinline__ void ldsm4(uint32_t* d, uint32_t a) {
    asm volatile("ldmatrix.sync.aligned.m8n8.x4.shared.b16 {%0,%1,%2,%3}, [%4];"
                 : "=r"(d[0]), "=r"(d[1]), "=r"(d[2]), "=r"(d[3]) : "r"(a));
}
__device__ __forceinline__ void ldsm4t(uint32_t* d, uint32_t a) {
    asm volatile("ldmatrix.sync.aligned.m8n8.x4.trans.shared.b16 {%0,%1,%2,%3}, [%4];"
                 : "=r"(d[0]), "=r"(d[1]), "=r"(d[2]), "=r"(d[3]) : "r"(a));
}
__device__ __forceinline__ void mma_f16(float* c, const uint32_t* a, uint32_t b0, uint32_t b1) {
    asm volatile("mma.sync.aligned.m16n8k16.row.col.f32.f16.f16.f32 "
                 "{%0,%1,%2,%3}, {%4,%5,%6,%7}, {%8,%9}, {%0,%1,%2,%3};"
                 : "+f"(c[0]), "+f"(c[1]), "+f"(c[2]), "+f"(c[3])
                 : "r"(a[0]), "r"(a[1]), "r"(a[2]), "r"(a[3]), "r"(b0), "r"(b1));
}
__device__ __forceinline__ uint32_t h2u(__half2 h) { return *reinterpret_cast<uint32_t*>(&h); }
__device__ __forceinline__ void splith(float a, float b, uint32_t& hi, uint32_t& lo) {
    __half2 h = __floats2half2_rn(a, b);
    float2 f = __half22float2(h);
    __half2 l = __floats2half2_rn(a - f.x, b - f.y);
    hi = h2u(h);
    lo = h2u(l);
}

// ---------------------------------------------------------------------------
// Kernel 1: norms -> shift (log2-domain); fp16 Q*SCALE2, split Kn, fp16 V.
// ---------------------------------------------------------------------------
__global__ void prep_kernel(const float* __restrict__ qk, const float* __restrict__ v) {
    int row = blockIdx.x * 8 + (threadIdx.x >> 5);
    int lane = threadIdx.x & 31;
    float2 q = *(const float2*)(qk + (size_t)row * ND + lane * 2);
    float ss = q.x * q.x + q.y * q.y;
    #pragma unroll
    for (int o = 16; o >= 1; o >>= 1) ss += __shfl_xor_sync(0xffffffffu, ss, o);
    float nrm = fmaxf(sqrtf(ss), 1e-12f);
    float inv = 1.0f / nrm;
    size_t w = (size_t)row * 32 + lane;
    g_qh[w] = h2u(__floats2half2_rn(q.x * SCALE2, q.y * SCALE2));
    uint32_t hi, lo;
    splith(q.x * inv, q.y * inv, hi, lo);
    g_kh[w] = hi; g_kl[w] = lo;
    float2 vv = *(const float2*)(v + (size_t)row * ND + lane * 2);
    g_vh[w] = h2u(__floats2half2_rn(vv.x, vv.y));
    if (lane == 0) g_shift[row] = nrm * SCALE2;
}

// ---------------------------------------------------------------------------
// Kernel 2: fused attention (R10 shape: 64-row strips, 256 CTAs, 8 warps).
// Phase 0: 1-term S pass -> rowsum (no stores). Phase 1: 2-term S -> exp2 ->
// NORMALIZED attn store (single write, no sweep) -> AV -> normalized out.
// Q fragments register-resident; 3-buffer cp.async ring; 1 barrier/tile.
// ---------------------------------------------------------------------------
__global__ __launch_bounds__(256, 2)
void attn_main(const float* __restrict__ v,
               float* __restrict__ out, float* __restrict__ attn)
{
    extern __shared__ char smc[];
    const uint32_t sb = smem_u32(smc);
    const int tid = threadIdx.x, lane = tid & 31, w = tid >> 5;
    const int wy = w & 3, wx = w >> 2;   // row group (16 rows), col half (32 j-cols)

    // balanced schedule: paired SMs sum to 65 tile-iters
    int l = blockIdx.x, rt, b;
    if (l < 40)       { rt = 63 - (l >> 2); b = l & 3; }
    else if (l < 148) { int i = l - 40; rt = 53 - (i >> 2); b = i & 3; }
    else              { int i = l - 148; rt = i >> 2; b = i & 3; }
    const size_t bS = (size_t)b * NS;
    const int nt = rt + 1;

    __shared__ float rspart[2][64];
    __shared__ float inv_s[64];

    const uint64_t gqh = gaddr(g_qh);
    const uint64_t gkh = gaddr(g_kh), gkl = gaddr(g_kl);
    const uint64_t gvh = gaddr(g_vh);

    auto issue_kv = [&](int ct, uint32_t buf) {
        size_t t0 = (bS + (size_t)ct * 64) * 128;
        uint32_t kb = sb + O_B + buf * BUFB;
        #pragma unroll
        for (int c = 0; c < 2; ++c) {
            int idx = tid * 2 + c, r = idx >> 3, c8 = idx & 7;
            uint32_t so = (uint32_t)(r * 144 + c8 * 16);
            uint64_t go = t0 + (size_t)r * 128 + c8 * 16;
            cp16(kb + so, gkh + go);
            cp16(kb + TBYTES + so, gkl + go);
            cp16(kb + 2 * TBYTES + so, gvh + go);
        }
    };

    // ldmatrix byte-offset helpers (within a tile)
    const uint32_t A_off = (uint32_t)(((lane & 15) * STR + ((lane >> 4) << 3)) * 2);
    const uint32_t B_off = (uint32_t)(((((lane >> 4) << 3) + (lane & 7)) * STR + (((lane >> 3) & 1) << 3)) * 2);

    const int g = lane >> 2, t = lane & 3;
    const int r0 = wy * 16 + g;
    const int gi0 = rt * 64 + r0, gi1 = gi0 + 8;
    const float sh0 = g_shift[bS + gi0];
    const float sh1 = g_shift[bS + gi1];
    float* attn_b = attn + (size_t)b * NS * NS;
    float* arow0 = attn_b + (size_t)gi0 * NS;
    float* arow1 = attn_b + (size_t)gi1 * NS;

    // ---------------- prologue: Q + tiles 0,1 ----------------
    {
        size_t q0 = (bS + (size_t)rt * 64) * 128;
        #pragma unroll
        for (int c = 0; c < 2; ++c) {
            int idx = tid * 2 + c, r = idx >> 3, c8 = idx & 7;
            cp16(sb + O_Q + (uint32_t)(r * 144 + c8 * 16),
                 gqh + q0 + (size_t)r * 128 + c8 * 16);
        }
        issue_kv(0, 0);
        CP_COMMIT();
        if (nt > 1) issue_kv(1, 1);
        CP_COMMIT();
    }
    CP_WAIT1();              // Q + tile0 complete
    __syncthreads();

    // --- Q fragments -> registers (loop-invariant, both phases) ---
    uint32_t aqf[4][4];
    {
        const uint32_t qo = sb + O_Q + A_off + (uint32_t)(wy * 16 * STR * 2);
        #pragma unroll
        for (int k = 0; k < 4; ++k) ldsm4(aqf[k], qo + (uint32_t)(k * 32));
    }

    // ================= PHASE 0: 1-term rowsum pass =================
    {
        float rs0 = 0.f, rs1 = 0.f;
        for (int ct = 0; ct < nt; ++ct) {
            const uint32_t buf = (uint32_t)(ct % 3);
            if (ct) { CP_WAIT1(); __syncthreads(); }
            if (ct + 2 < nt) issue_kv(ct + 2, (uint32_t)((ct + 2) % 3));
            CP_COMMIT();

            float sc[4][4] = {};
            const uint32_t khb = sb + O_B + buf * BUFB + (uint32_t)(wx * 32 * STR * 2);
            #pragma unroll
            for (int k = 0; k < 4; ++k) {
                uint32_t bh[4];
                uint32_t kcol = (uint32_t)(k * 32);
                #pragma unroll
                for (int np = 0; np < 2; ++np) {
                    ldsm4(bh, khb + B_off + (uint32_t)(np * 16 * STR * 2) + kcol);
                    mma_f16(sc[2 * np],     aqf[k], bh[0], bh[1]);
                    mma_f16(sc[2 * np + 1], aqf[k], bh[2], bh[3]);
                }
            }
            const int gjb = ct * 64 + wx * 32 + 2 * t;
            #pragma unroll
            for (int nb = 0; nb < 4; ++nb) {
                int gj = gjb + nb * 8;
                if (gj < gi0)     rs0 += exp2f(sc[nb][0] - sh0);
                if (gj + 1 < gi0) rs0 += exp2f(sc[nb][1] - sh0);
                if (gj < gi1)     rs1 += exp2f(sc[nb][2] - sh1);
                if (gj + 1 < gi1) rs1 += exp2f(sc[nb][3] - sh1);
            }
        }
        CP_WAIT0();
        __syncthreads();     // all phase-0 buffer reads done
        rs0 += __shfl_xor_sync(0xffffffffu, rs0, 1);
        rs0 += __shfl_xor_sync(0xffffffffu, rs0, 2);
        rs1 += __shfl_xor_sync(0xffffffffu, rs1, 1);
        rs1 += __shfl_xor_sync(0xffffffffu, rs1, 2);
        if (t == 0) {
            rspart[wx][r0] = rs0;
            rspart[wx][r0 + 8] = rs1;
        }
        __syncthreads();
        if (tid < 64) {
            float rs = rspart[0][tid] + rspart[1][tid];
            inv_s[tid] = rs > 0.f ? 1.0f / rs : 0.f;
        }
        __syncthreads();
    }
    const float inv0 = inv_s[r0];
    const float inv1 = inv_s[r0 + 8];

    // ================= PHASE 1: normalized write + AV =================
    {
        size_t q0 = 0; (void)q0;
        issue_kv(0, 0);
        CP_COMMIT();
        if (nt > 1) issue_kv(1, 1);
        CP_COMMIT();
    }

    float oc[8][4] = {};       // partial O[16 x 64] over this warp's j-half
    for (int ct = 0; ct < nt; ++ct) {
        const uint32_t buf = (uint32_t)(ct % 3);
        CP_WAIT1();
        __syncthreads();
        if (ct + 2 < nt) issue_kv(ct + 2, (uint32_t)((ct + 2) % 3));
        CP_COMMIT();

        // --- preload this warp's V fragments (rows wx*32.., 64 e-cols) ---
        uint32_t vfr0[4][4], vfr1[4][4];
        const uint32_t vhb = sb + O_B + buf * BUFB + 2 * TBYTES
                           + (uint32_t)(wx * 32 * STR * 2);
        #pragma unroll
        for (int ep = 0; ep < 4; ++ep)
            ldsm4t(vfr0[ep], vhb + A_off + (uint32_t)(ep * 32));

        // --- S[16x32] = Qs @ Kn^T (2-term, Q from registers) ---
        float sc[4][4] = {};
        const uint32_t khb = sb + O_B + buf * BUFB + (uint32_t)(wx * 32 * STR * 2);
        const uint32_t klb = khb + TBYTES;
        #pragma unroll
        for (int k = 0; k < 4; ++k) {
            uint32_t bh[4], bl[4];
            uint32_t kcol = (uint32_t)(k * 32);
            #pragma unroll
            for (int np = 0; np < 2; ++np) {
                uint32_t jo = (uint32_t)(np * 16 * STR * 2);
                ldsm4(bh, khb + B_off + jo + kcol);
                ldsm4(bl, klb + B_off + jo + kcol);
                mma_f16(sc[2 * np],     aqf[k], bh[0], bh[1]);
                mma_f16(sc[2 * np],     aqf[k], bl[0], bl[1]);
                mma_f16(sc[2 * np + 1], aqf[k], bh[2], bh[3]);
                mma_f16(sc[2 * np + 1], aqf[k], bl[2], bl[3]);
            }
        }
        #pragma unroll
        for (int ep = 0; ep < 4; ++ep)
            ldsm4t(vfr1[ep], vhb + A_off + (uint32_t)(16 * STR * 2) + (uint32_t)(ep * 32));

        // --- exp2 * inv (normalized!) + attn store + fp16 A-frag repack ---
        uint32_t ah_[2][4];
        const int gjb = ct * 64 + wx * 32 + 2 * t;
        #pragma unroll
        for (int nb = 0; nb < 4; ++nb) {
            int gj = gjb + nb * 8;
            float p00 = (gj < gi0)     ? exp2f(sc[nb][0] - sh0) * inv0 : 0.f;
            float p01 = (gj + 1 < gi0) ? exp2f(sc[nb][1] - sh0) * inv0 : 0.f;
            float p10 = (gj < gi1)     ? exp2f(sc[nb][2] - sh1) * inv1 : 0.f;
            float p11 = (gj + 1 < gi1) ? exp2f(sc[nb][3] - sh1) * inv1 : 0.f;
            *(float2*)(arow0 + gj) = make_float2(p00, p01);
            *(float2*)(arow1 + gj) = make_float2(p10, p11);
            int kb = nb >> 1, o = (nb & 1) * 2;
            ah_[kb][o]     = h2u(__floats2half2_rn(p00, p01));
            ah_[kb][o + 1] = h2u(__floats2half2_rn(p10, p11));
        }

        // --- O += P_norm @ V (already normalized) ---
        #pragma unroll
        for (int ep = 0; ep < 4; ++ep) {
            mma_f16(oc[2 * ep],     ah_[0], vfr0[ep][0], vfr0[ep][1]);
            mma_f16(oc[2 * ep + 1], ah_[0], vfr0[ep][2], vfr0[ep][3]);
            mma_f16(oc[2 * ep],     ah_[1], vfr1[ep][0], vfr1[ep][1]);
            mma_f16(oc[2 * ep + 1], ah_[1], vfr1[ep][2], vfr1[ep][3]);
        }
    }
    __syncthreads();   // all loop reads done (KV region free for obuf)

    // ---- combine column-half O partials via padded smem buffer ----
    float* obuf = (float*)(smc + O_B);   // 64 x 66 floats
    if (wx == 1) {
        #pragma unroll
        for (int nb = 0; nb < 8; ++nb) {
            int c = nb * 8 + 2 * t;
            obuf[r0 * 66 + c]           = oc[nb][0];
            obuf[r0 * 66 + c + 1]       = oc[nb][1];
            obuf[(r0 + 8) * 66 + c]     = oc[nb][2];
            obuf[(r0 + 8) * 66 + c + 1] = oc[nb][3];
        }
    }
    __syncthreads();
    if (wx == 0) {
        float* o0 = out + (bS + gi0) * ND;
        float* o1 = out + (bS + gi1) * ND;
        if (gi0 == 0) {
            const float* vr = v + bS * ND;  // row 0: softmax over single -50000 diag
            #pragma unroll
            for (int nb = 0; nb < 8; ++nb) {
                int c = nb * 8 + 2 * t;
                *(float2*)(o0 + c) = *(const float2*)(vr + c);
            }
        } else {
            #pragma unroll
            for (int nb = 0; nb < 8; ++nb) {
                int c = nb * 8 + 2 * t;
                *(float2*)(o0 + c) = make_float2(oc[nb][0] + obuf[r0 * 66 + c],
                                                 oc[nb][1] + obuf[r0 * 66 + c + 1]);
            }
        }
        #pragma unroll
        for (int nb = 0; nb < 8; ++nb) {
            int c = nb * 8 + 2 * t;
            *(float2*)(o1 + c) = make_float2(oc[nb][2] + obuf[(r0 + 8) * 66 + c],
                                             oc[nb][3] + obuf[(r0 + 8) * 66 + c + 1]);
        }
    }

    // ---- upper-triangle zero-fill (anti-correlated with compute) ----
    {
        int r = tid >> 2;
        float* rowp = attn_b + (size_t)(rt * 64 + r) * NS;
        float4 z = make_float4(0.f, 0.f, 0.f, 0.f);
        for (int c = nt * 64 + (tid & 3) * 4; c < NS; c += 16)
            *(float4*)(rowp + c) = z;
    }
    if (rt == 0 && tid == 0) attn_b[0] = 1.0f;  // row 0: softmax over single diag entry
}

// ---------------------------------------------------------------------------
extern "C" void kernel_launch(void* const* d_in, const int* in_sizes, int n_in,
                              void* d_out, int out_size) {
    const float* qk = (const float*)d_in[0];
    const float* v  = (const float*)d_in[1];
    float* out  = (float*)d_out;
    float* attn = out + (size_t)NB * NS * ND;

    cudaFuncSetAttribute(attn_main, cudaFuncAttributeMaxDynamicSharedMemorySize, SMEM_SZ);
    prep_kernel<<<NB * NS / 8, 256>>>(qk, v);
    attn_main<<<256, 256, SMEM_SZ>>>(v, out, attn);
}

// round 14
// speedup vs baseline: 1.2995x; 1.2129x over previous
#include <cuda_runtime.h>
#include <cuda_fp16.h>
#include <cstdint>

#define NB 4
#define NS 4096
#define ND 64
#define SCALE2 0.18033688f   // 0.125 * log2(e): exp(x*0.125) = exp2(x*SCALE2)
#define STR 72u              // fp16 elems per smem row (144 B -> LDSM conflict-free)
#define TBYTES 9216u         // one 64x72 fp16 tile
#define BUFB 27648u          // one buffer group: KH + KL + VH

// dynamic smem: [Q 9216][3 x (KH, KL, VH)]; O-combine buffer reuses KV region
#define O_Q 0u
#define O_B 9216u
#define SMEM_SZ 92160u

// pre-split fp16 operand arrays (uint32 = fp16x2), rows of 128 B
__device__ __align__(128) uint32_t g_qh[(size_t)NB * NS * 32];  // fp16(q*SCALE2)
__device__ __align__(128) uint32_t g_kh[(size_t)NB * NS * 32];  // fp16 hi of kn
__device__ __align__(128) uint32_t g_kl[(size_t)NB * NS * 32];  // fp16 lo of kn
__device__ __align__(128) uint32_t g_vh[(size_t)NB * NS * 32];  // fp16(v)
__device__ float g_shift[NB * NS];

// ------------------------------------------------------------- PTX helpers
__device__ __forceinline__ uint32_t smem_u32(const void* p) {
    uint32_t a;
    asm("{ .reg .u64 t; cvta.to.shared.u64 t, %1; cvt.u32.u64 %0, t; }" : "=r"(a) : "l"(p));
    return a;
}
__device__ __forceinline__ uint64_t gaddr(const void* p) {
    uint64_t a;
    asm("cvta.to.global.u64 %0, %1;" : "=l"(a) : "l"(p));
    return a;
}
__device__ __forceinline__ void cp16(uint32_t dst, uint64_t src) {
    asm volatile("cp.async.cg.shared.global [%0], [%1], 16;" ::"r"(dst), "l"(src));
}
#define CP_COMMIT() asm volatile("cp.async.commit_group;" ::: "memory")
#define CP_WAIT1()  asm volatile("cp.async.wait_group 1;" ::: "memory")
#define CP_WAIT0()  asm volatile("cp.async.wait_group 0;" ::: "memory")

__device__ __forceinline__ void ldsm4(uint32_t* d, uint32_t a) {
    asm volatile("ldmatrix.sync.aligned.m8n8.x4.shared.b16 {%0,%1,%2,%3}, [%4];"
                 : "=r"(d[0]), "=r"(d[1]), "=r"(d[2]), "=r"(d[3]) : "r"(a));
}
__device__ __forceinline__ void ldsm4t(uint32_t* d, uint32_t a) {
    asm volatile("ldmatrix.sync.aligned.m8n8.x4.trans.shared.b16 {%0,%1,%2,%3}, [%4];"
                 : "=r"(d[0]), "=r"(d[1]), "=r"(d[2]), "=r"(d[3]) : "r"(a));
}
__device__ __forceinline__ void mma_f16(float* c, const uint32_t* a, uint32_t b0, uint32_t b1) {
    asm volatile("mma.sync.aligned.m16n8k16.row.col.f32.f16.f16.f32 "
                 "{%0,%1,%2,%3}, {%4,%5,%6,%7}, {%8,%9}, {%0,%1,%2,%3};"
                 : "+f"(c[0]), "+f"(c[1]), "+f"(c[2]), "+f"(c[3])
                 : "r"(a[0]), "r"(a[1]), "r"(a[2]), "r"(a[3]), "r"(b0), "r"(b1));
}
__device__ __forceinline__ uint32_t h2u(__half2 h) { return *reinterpret_cast<uint32_t*>(&h); }
__device__ __forceinline__ void splith(float a, float b, uint32_t& hi, uint32_t& lo) {
    __half2 h = __floats2half2_rn(a, b);
    float2 f = __half22float2(h);
    __half2 l = __floats2half2_rn(a - f.x, b - f.y);
    hi = h2u(h);
    lo = h2u(l);
}

// ---------------------------------------------------------------------------
// Kernel 1: norms -> shift (log2-domain); fp16 Q*SCALE2, split Kn, fp16 V.
// ---------------------------------------------------------------------------
__global__ void prep_kernel(const float* __restrict__ qk, const float* __restrict__ v) {
    int row = blockIdx.x * 8 + (threadIdx.x >> 5);
    int lane = threadIdx.x & 31;
    float2 q = *(const float2*)(qk + (size_t)row * ND + lane * 2);
    float ss = q.x * q.x + q.y * q.y;
    #pragma unroll
    for (int o = 16; o >= 1; o >>= 1) ss += __shfl_xor_sync(0xffffffffu, ss, o);
    float nrm = fmaxf(sqrtf(ss), 1e-12f);
    float inv = 1.0f / nrm;
    size_t w = (size_t)row * 32 + lane;
    g_qh[w] = h2u(__floats2half2_rn(q.x * SCALE2, q.y * SCALE2));
    uint32_t hi, lo;
    splith(q.x * inv, q.y * inv, hi, lo);
    g_kh[w] = hi; g_kl[w] = lo;
    float2 vv = *(const float2*)(v + (size_t)row * ND + lane * 2);
    g_vh[w] = h2u(__floats2half2_rn(vv.x, vv.y));
    if (lane == 0) g_shift[row] = nrm * SCALE2;
}

// ---------------------------------------------------------------------------
// Kernel 2: fused attention (64-row strips, 256 CTAs, 8 warps).
// Phase 0: 1-term S (KH-only loads) -> rowsum. Phase 1: 2-term S -> exp2 ->
// NORMALIZED attn store -> AV -> out. Diagonal tile specialized; all other
// tiles run branch-free (no mask compares).
// ---------------------------------------------------------------------------
__global__ __launch_bounds__(256, 2)
void attn_main(const float* __restrict__ v,
               float* __restrict__ out, float* __restrict__ attn)
{
    extern __shared__ char smc[];
    const uint32_t sb = smem_u32(smc);
    const int tid = threadIdx.x, lane = tid & 31, w = tid >> 5;
    const int wy = w & 3, wx = w >> 2;   // row group (16 rows), col half (32 j-cols)

    // balanced schedule: paired SMs sum to 65 tile-iters
    int l = blockIdx.x, rt, b;
    if (l < 40)       { rt = 63 - (l >> 2); b = l & 3; }
    else if (l < 148) { int i = l - 40; rt = 53 - (i >> 2); b = i & 3; }
    else              { int i = l - 148; rt = i >> 2; b = i & 3; }
    const size_t bS = (size_t)b * NS;
    const int nt = rt + 1;

    __shared__ float rspart[2][64];
    __shared__ float inv_s[64];

    const uint64_t gqh = gaddr(g_qh);
    const uint64_t gkh = gaddr(g_kh), gkl = gaddr(g_kl);
    const uint64_t gvh = gaddr(g_vh);

    auto issue_kv = [&](int ct, uint32_t buf) {   // full group (phase 1)
        size_t t0 = (bS + (size_t)ct * 64) * 128;
        uint32_t kb = sb + O_B + buf * BUFB;
        #pragma unroll
        for (int c = 0; c < 2; ++c) {
            int idx = tid * 2 + c, r = idx >> 3, c8 = idx & 7;
            uint32_t so = (uint32_t)(r * 144 + c8 * 16);
            uint64_t go = t0 + (size_t)r * 128 + c8 * 16;
            cp16(kb + so, gkh + go);
            cp16(kb + TBYTES + so, gkl + go);
            cp16(kb + 2 * TBYTES + so, gvh + go);
        }
    };
    auto issue_k = [&](int ct, uint32_t buf) {    // KH only (phase 0)
        size_t t0 = (bS + (size_t)ct * 64) * 128;
        uint32_t kb = sb + O_B + buf * BUFB;
        #pragma unroll
        for (int c = 0; c < 2; ++c) {
            int idx = tid * 2 + c, r = idx >> 3, c8 = idx & 7;
            cp16(kb + (uint32_t)(r * 144 + c8 * 16),
                 gkh + t0 + (size_t)r * 128 + c8 * 16);
        }
    };

    // ldmatrix byte-offset helpers (within a tile)
    const uint32_t A_off = (uint32_t)(((lane & 15) * STR + ((lane >> 4) << 3)) * 2);
    const uint32_t B_off = (uint32_t)(((((lane >> 4) << 3) + (lane & 7)) * STR + (((lane >> 3) & 1) << 3)) * 2);

    const int g = lane >> 2, t = lane & 3;
    const int r0 = wy * 16 + g;
    const int gi0 = rt * 64 + r0, gi1 = gi0 + 8;
    const float sh0 = g_shift[bS + gi0];
    const float sh1 = g_shift[bS + gi1];
    float* attn_b = attn + (size_t)b * NS * NS;
    float* arow0 = attn_b + (size_t)gi0 * NS;
    float* arow1 = attn_b + (size_t)gi1 * NS;

    // ---------------- prologue: Q + K tiles 0,1 ----------------
    {
        size_t q0 = (bS + (size_t)rt * 64) * 128;
        #pragma unroll
        for (int c = 0; c < 2; ++c) {
            int idx = tid * 2 + c, r = idx >> 3, c8 = idx & 7;
            cp16(sb + O_Q + (uint32_t)(r * 144 + c8 * 16),
                 gqh + q0 + (size_t)r * 128 + c8 * 16);
        }
        issue_k(0, 0);
        CP_COMMIT();
        if (nt > 1) issue_k(1, 1);
        CP_COMMIT();
    }
    CP_WAIT1();              // Q + K tile0 complete
    __syncthreads();

    // --- Q fragments -> registers (loop-invariant, both phases) ---
    uint32_t aqf[4][4];
    {
        const uint32_t qo = sb + O_Q + A_off + (uint32_t)(wy * 16 * STR * 2);
        #pragma unroll
        for (int k = 0; k < 4; ++k) ldsm4(aqf[k], qo + (uint32_t)(k * 32));
    }

    // ================= PHASE 0: 1-term rowsum pass (KH only) =================
    {
        float rs0 = 0.f, rs1 = 0.f;
        for (int ct = 0; ct < nt; ++ct) {
            const uint32_t buf = (uint32_t)(ct % 3);
            if (ct) { CP_WAIT1(); __syncthreads(); }
            if (ct + 2 < nt) issue_k(ct + 2, (uint32_t)((ct + 2) % 3));
            CP_COMMIT();

            float sc[4][4] = {};
            const uint32_t khb = sb + O_B + buf * BUFB + (uint32_t)(wx * 32 * STR * 2);
            #pragma unroll
            for (int k = 0; k < 4; ++k) {
                uint32_t bh[4];
                uint32_t kcol = (uint32_t)(k * 32);
                #pragma unroll
                for (int np = 0; np < 2; ++np) {
                    ldsm4(bh, khb + B_off + (uint32_t)(np * 16 * STR * 2) + kcol);
                    mma_f16(sc[2 * np],     aqf[k], bh[0], bh[1]);
                    mma_f16(sc[2 * np + 1], aqf[k], bh[2], bh[3]);
                }
            }
            if (ct != rt) {
                // fully-unmasked tile: branch-free accumulation
                #pragma unroll
                for (int nb = 0; nb < 4; ++nb) {
                    rs0 += exp2f(sc[nb][0] - sh0) + exp2f(sc[nb][1] - sh0);
                    rs1 += exp2f(sc[nb][2] - sh1) + exp2f(sc[nb][3] - sh1);
                }
            } else {
                const int gjb = ct * 64 + wx * 32 + 2 * t;
                #pragma unroll
                for (int nb = 0; nb < 4; ++nb) {
                    int gj = gjb + nb * 8;
                    if (gj < gi0)     rs0 += exp2f(sc[nb][0] - sh0);
                    if (gj + 1 < gi0) rs0 += exp2f(sc[nb][1] - sh0);
                    if (gj < gi1)     rs1 += exp2f(sc[nb][2] - sh1);
                    if (gj + 1 < gi1) rs1 += exp2f(sc[nb][3] - sh1);
                }
            }
        }
        CP_WAIT0();
        __syncthreads();     // all phase-0 buffer reads done
        rs0 += __shfl_xor_sync(0xffffffffu, rs0, 1);
        rs0 += __shfl_xor_sync(0xffffffffu, rs0, 2);
        rs1 += __shfl_xor_sync(0xffffffffu, rs1, 1);
        rs1 += __shfl_xor_sync(0xffffffffu, rs1, 2);
        if (t == 0) {
            rspart[wx][r0] = rs0;
            rspart[wx][r0 + 8] = rs1;
        }
        __syncthreads();
        if (tid < 64) {
            float rs = rspart[0][tid] + rspart[1][tid];
            inv_s[tid] = rs > 0.f ? 1.0f / rs : 0.f;
        }
        __syncthreads();
    }
    const float inv0 = inv_s[r0];
    const float inv1 = inv_s[r0 + 8];

    // ================= PHASE 1: normalized write + AV =================
    issue_kv(0, 0);
    CP_COMMIT();
    if (nt > 1) issue_kv(1, 1);
    CP_COMMIT();

    float oc[8][4] = {};       // partial O[16 x 64] over this warp's j-half
    for (int ct = 0; ct < nt; ++ct) {
        const uint32_t buf = (uint32_t)(ct % 3);
        CP_WAIT1();
        __syncthreads();
        if (ct + 2 < nt) issue_kv(ct + 2, (uint32_t)((ct + 2) % 3));
        CP_COMMIT();

        // --- preload this warp's V fragments (rows wx*32.., 64 e-cols) ---
        uint32_t vfr0[4][4], vfr1[4][4];
        const uint32_t vhb = sb + O_B + buf * BUFB + 2 * TBYTES
                           + (uint32_t)(wx * 32 * STR * 2);
        #pragma unroll
        for (int ep = 0; ep < 4; ++ep)
            ldsm4t(vfr0[ep], vhb + A_off + (uint32_t)(ep * 32));

        // --- S[16x32] = Qs @ Kn^T (2-term, Q from registers) ---
        float sc[4][4] = {};
        const uint32_t khb = sb + O_B + buf * BUFB + (uint32_t)(wx * 32 * STR * 2);
        const uint32_t klb = khb + TBYTES;
        #pragma unroll
        for (int k = 0; k < 4; ++k) {
            uint32_t bh[4], bl[4];
            uint32_t kcol = (uint32_t)(k * 32);
            #pragma unroll
            for (int np = 0; np < 2; ++np) {
                uint32_t jo = (uint32_t)(np * 16 * STR * 2);
                ldsm4(bh, khb + B_off + jo + kcol);
                ldsm4(bl, klb + B_off + jo + kcol);
                mma_f16(sc[2 * np],     aqf[k], bh[0], bh[1]);
                mma_f16(sc[2 * np],     aqf[k], bl[0], bl[1]);
                mma_f16(sc[2 * np + 1], aqf[k], bh[2], bh[3]);
                mma_f16(sc[2 * np + 1], aqf[k], bl[2], bl[3]);
            }
        }
        #pragma unroll
        for (int ep = 0; ep < 4; ++ep)
            ldsm4t(vfr1[ep], vhb + A_off + (uint32_t)(16 * STR * 2) + (uint32_t)(ep * 32));

        // --- exp2 * inv (normalized) + attn store + fp16 A-frag repack ---
        uint32_t ah_[2][4];
        const int gjb = ct * 64 + wx * 32 + 2 * t;
        if (ct != rt) {
            // fully-unmasked tile: branch-free
            #pragma unroll
            for (int nb = 0; nb < 4; ++nb) {
                int gj = gjb + nb * 8;
                float p00 = exp2f(sc[nb][0] - sh0) * inv0;
                float p01 = exp2f(sc[nb][1] - sh0) * inv0;
                float p10 = exp2f(sc[nb][2] - sh1) * inv1;
                float p11 = exp2f(sc[nb][3] - sh1) * inv1;
                *(float2*)(arow0 + gj) = make_float2(p00, p01);
                *(float2*)(arow1 + gj) = make_float2(p10, p11);
                int kb = nb >> 1, o = (nb & 1) * 2;
                ah_[kb][o]     = h2u(__floats2half2_rn(p00, p01));
                ah_[kb][o + 1] = h2u(__floats2half2_rn(p10, p11));
            }
        } else {
            #pragma unroll
            for (int nb = 0; nb < 4; ++nb) {
                int gj = gjb + nb * 8;
                float p00 = (gj < gi0)     ? exp2f(sc[nb][0] - sh0) * inv0 : 0.f;
                float p01 = (gj + 1 < gi0) ? exp2f(sc[nb][1] - sh0) * inv0 : 0.f;
                float p10 = (gj < gi1)     ? exp2f(sc[nb][2] - sh1) * inv1 : 0.f;
                float p11 = (gj + 1 < gi1) ? exp2f(sc[nb][3] - sh1) * inv1 : 0.f;
                *(float2*)(arow0 + gj) = make_float2(p00, p01);
                *(float2*)(arow1 + gj) = make_float2(p10, p11);
                int kb = nb >> 1, o = (nb & 1) * 2;
                ah_[kb][o]     = h2u(__floats2half2_rn(p00, p01));
                ah_[kb][o + 1] = h2u(__floats2half2_rn(p10, p11));
            }
        }

        // --- O += P_norm @ V ---
        #pragma unroll
        for (int ep = 0; ep < 4; ++ep) {
            mma_f16(oc[2 * ep],     ah_[0], vfr0[ep][0], vfr0[ep][1]);
            mma_f16(oc[2 * ep + 1], ah_[0], vfr0[ep][2], vfr0[ep][3]);
            mma_f16(oc[2 * ep],     ah_[1], vfr1[ep][0], vfr1[ep][1]);
            mma_f16(oc[2 * ep + 1], ah_[1], vfr1[ep][2], vfr1[ep][3]);
        }
    }
    __syncthreads();   // all loop reads done (KV region free for obuf)

    // ---- combine column-half O partials via padded smem buffer ----
    float* obuf = (float*)(smc + O_B);   // 64 x 66 floats
    if (wx == 1) {
        #pragma unroll
        for (int nb = 0; nb < 8; ++nb) {
            int c = nb * 8 + 2 * t;
            obuf[r0 * 66 + c]           = oc[nb][0];
            obuf[r0 * 66 + c + 1]       = oc[nb][1];
            obuf[(r0 + 8) * 66 + c]     = oc[nb][2];
            obuf[(r0 + 8) * 66 + c + 1] = oc[nb][3];
        }
    }
    __syncthreads();
    if (wx == 0) {
        float* o0 = out + (bS + gi0) * ND;
        float* o1 = out + (bS + gi1) * ND;
        if (gi0 == 0) {
            const float* vr = v + bS * ND;  // row 0: softmax over single -50000 diag
            #pragma unroll
            for (int nb = 0; nb < 8; ++nb) {
                int c = nb * 8 + 2 * t;
                *(float2*)(o0 + c) = *(const float2*)(vr + c);
            }
        } else {
            #pragma unroll
            for (int nb = 0; nb < 8; ++nb) {
                int c = nb * 8 + 2 * t;
                *(float2*)(o0 + c) = make_float2(oc[nb][0] + obuf[r0 * 66 + c],
                                                 oc[nb][1] + obuf[r0 * 66 + c + 1]);
            }
        }
        #pragma unroll
        for (int nb = 0; nb < 8; ++nb) {
            int c = nb * 8 + 2 * t;
            *(float2*)(o1 + c) = make_float2(oc[nb][2] + obuf[(r0 + 8) * 66 + c],
                                             oc[nb][3] + obuf[(r0 + 8) * 66 + c + 1]);
        }
    }

    // ---- upper-triangle zero-fill (anti-correlated with compute) ----
    {
        int r = tid >> 2;
        float* rowp = attn_b + (size_t)(rt * 64 + r) * NS;
        float4 z = make_float4(0.f, 0.f, 0.f, 0.f);
        for (int c = nt * 64 + (tid & 3) * 4; c < NS; c += 16)
            *(float4*)(rowp + c) = z;
    }
    if (rt == 0 && tid == 0) attn_b[0] = 1.0f;  // row 0: softmax over single diag entry
}

// ---------------------------------------------------------------------------
extern "C" void kernel_launch(void* const* d_in, const int* in_sizes, int n_in,
                              void* d_out, int out_size) {
    const float* qk = (const float*)d_in[0];
    const float* v  = (const float*)d_in[1];
    float* out  = (float*)d_out;
    float* attn = out + (size_t)NB * NS * ND;

    cudaFuncSetAttribute(attn_main, cudaFuncAttributeMaxDynamicSharedMemorySize, SMEM_SZ);
    prep_kernel<<<NB * NS / 8, 256>>>(qk, v);
    attn_main<<<256, 256, SMEM_SZ>>>(v, out, attn);
}

// round 15
// speedup vs baseline: 1.3748x; 1.0580x over previous
#include <cuda_runtime.h>
#include <cuda_fp16.h>
#include <cstdint>

#define NB 4
#define NS 4096
#define ND 64
#define SCALE2 0.18033688f   // 0.125 * log2(e): exp(x*0.125) = exp2(x*SCALE2)
#define STR 72u              // fp16 elems per smem row (144 B -> LDSM conflict-free)
#define TBYTES 9216u         // one 64x72 fp16 tile
#define BUFB 27648u          // one buffer group: KH+KL+VH (phase1) / 3 KH tiles (phase0)

// dynamic smem: [Q 9216][3 x BUFB]
#define O_Q 0u
#define O_B 9216u
#define SMEM_SZ 92160u

// pre-split fp16 operand arrays (uint32 = fp16x2), rows of 128 B
__device__ __align__(128) uint32_t g_qh[(size_t)NB * NS * 32];  // fp16(q*SCALE2)
__device__ __align__(128) uint32_t g_kh[(size_t)NB * NS * 32];  // fp16 hi of kn
__device__ __align__(128) uint32_t g_kl[(size_t)NB * NS * 32];  // fp16 lo of kn
__device__ __align__(128) uint32_t g_vh[(size_t)NB * NS * 32];  // fp16(v)
__device__ float g_shift[NB * NS];

// ------------------------------------------------------------- PTX helpers
__device__ __forceinline__ uint32_t smem_u32(const void* p) {
    uint32_t a;
    asm("{ .reg .u64 t; cvta.to.shared.u64 t, %1; cvt.u32.u64 %0, t; }" : "=r"(a) : "l"(p));
    return a;
}
__device__ __forceinline__ uint64_t gaddr(const void* p) {
    uint64_t a;
    asm("cvta.to.global.u64 %0, %1;" : "=l"(a) : "l"(p));
    return a;
}
__device__ __forceinline__ void cp16(uint32_t dst, uint64_t src) {
    asm volatile("cp.async.cg.shared.global [%0], [%1], 16;" ::"r"(dst), "l"(src));
}
#define CP_COMMIT() asm volatile("cp.async.commit_group;" ::: "memory")
#define CP_WAIT1()  asm volatile("cp.async.wait_group 1;" ::: "memory")
#define CP_WAIT0()  asm volatile("cp.async.wait_group 0;" ::: "memory")

__device__ __forceinline__ void ldsm4(uint32_t* d, uint32_t a) {
    asm volatile("ldmatrix.sync.aligned.m8n8.x4.shared.b16 {%0,%1,%2,%3}, [%4];"
                 : "=r"(d[0]), "=r"(d[1]), "=r"(d[2]), "=r"(d[3]) : "r"(a));
}
__device__ __forceinline__ void ldsm4t(uint32_t* d, uint32_t a) {
    asm volatile("ldmatrix.sync.aligned.m8n8.x4.trans.shared.b16 {%0,%1,%2,%3}, [%4];"
                 : "=r"(d[0]), "=r"(d[1]), "=r"(d[2]), "=r"(d[3]) : "r"(a));
}
__device__ __forceinline__ void mma_f16(float* c, const uint32_t* a, uint32_t b0, uint32_t b1) {
    asm volatile("mma.sync.aligned.m16n8k16.row.col.f32.f16.f16.f32 "
                 "{%0,%1,%2,%3}, {%4,%5,%6,%7}, {%8,%9}, {%0,%1,%2,%3};"
                 : "+f"(c[0]), "+f"(c[1]), "+f"(c[2]), "+f"(c[3])
                 : "r"(a[0]), "r"(a[1]), "r"(a[2]), "r"(a[3]), "r"(b0), "r"(b1));
}
__device__ __forceinline__ uint32_t h2u(__half2 h) { return *reinterpret_cast<uint32_t*>(&h); }
__device__ __forceinline__ void splith(float a, float b, uint32_t& hi, uint32_t& lo) {
    __half2 h = __floats2half2_rn(a, b);
    float2 f = __half22float2(h);
    __half2 l = __floats2half2_rn(a - f.x, b - f.y);
    hi = h2u(h);
    lo = h2u(l);
}

// ---------------------------------------------------------------------------
// Kernel 1: norms -> shift (log2-domain); fp16 Q*SCALE2, split Kn, fp16 V.
// ---------------------------------------------------------------------------
__global__ void prep_kernel(const float* __restrict__ qk, const float* __restrict__ v) {
    int row = blockIdx.x * 8 + (threadIdx.x >> 5);
    int lane = threadIdx.x & 31;
    float2 q = *(const float2*)(qk + (size_t)row * ND + lane * 2);
    float ss = q.x * q.x + q.y * q.y;
    #pragma unroll
    for (int o = 16; o >= 1; o >>= 1) ss += __shfl_xor_sync(0xffffffffu, ss, o);
    float nrm = fmaxf(sqrtf(ss), 1e-12f);
    float inv = 1.0f / nrm;
    size_t w = (size_t)row * 32 + lane;
    g_qh[w] = h2u(__floats2half2_rn(q.x * SCALE2, q.y * SCALE2));
    uint32_t hi, lo;
    splith(q.x * inv, q.y * inv, hi, lo);
    g_kh[w] = hi; g_kl[w] = lo;
    float2 vv = *(const float2*)(v + (size_t)row * ND + lane * 2);
    g_vh[w] = h2u(__floats2half2_rn(vv.x, vv.y));
    if (lane == 0) g_shift[row] = nrm * SCALE2;
}

// ---------------------------------------------------------------------------
// Kernel 2: fused attention (64-row strips, 256 CTAs, 8 warps).
// Phase 0: 1-term S, KH-only, 3 tiles/buffer-group (1 barrier per 3 tiles).
// Phase 1: 2-term S -> exp2 -> NORMALIZED attn -> AV -> out. Diagonal tile
// specialized; phase-1 prologue loads overlap the rowsum reduction.
// ---------------------------------------------------------------------------
__global__ __launch_bounds__(256, 2)
void attn_main(const float* __restrict__ v,
               float* __restrict__ out, float* __restrict__ attn)
{
    extern __shared__ char smc[];
    const uint32_t sb = smem_u32(smc);
    const int tid = threadIdx.x, lane = tid & 31, w = tid >> 5;
    const int wy = w & 3, wx = w >> 2;   // row group (16 rows), col half (32 j-cols)

    // balanced schedule: paired SMs sum to 65 tile-iters
    int l = blockIdx.x, rt, b;
    if (l < 40)       { rt = 63 - (l >> 2); b = l & 3; }
    else if (l < 148) { int i = l - 40; rt = 53 - (i >> 2); b = i & 3; }
    else              { int i = l - 148; rt = i >> 2; b = i & 3; }
    const size_t bS = (size_t)b * NS;
    const int nt = rt + 1;

    __shared__ float rspart[2][64];
    __shared__ float inv_s[64];

    const uint64_t gqh = gaddr(g_qh);
    const uint64_t gkh = gaddr(g_kh), gkl = gaddr(g_kl);
    const uint64_t gvh = gaddr(g_vh);

    auto issue_kv = [&](int ct, uint32_t buf) {   // full group (phase 1)
        size_t t0 = (bS + (size_t)ct * 64) * 128;
        uint32_t kb = sb + O_B + buf * BUFB;
        #pragma unroll
        for (int c = 0; c < 2; ++c) {
            int idx = tid * 2 + c, r = idx >> 3, c8 = idx & 7;
            uint32_t so = (uint32_t)(r * 144 + c8 * 16);
            uint64_t go = t0 + (size_t)r * 128 + c8 * 16;
            cp16(kb + so, gkh + go);
            cp16(kb + TBYTES + so, gkl + go);
            cp16(kb + 2 * TBYTES + so, gvh + go);
        }
    };
    auto issue_k3 = [&](int c0, uint32_t buf) {   // 3 KH tiles (phase 0)
        uint32_t kb = sb + O_B + buf * BUFB;
        int idx0 = tid * 2, r = idx0 >> 3, c8 = idx0 & 7;
        uint32_t so0 = (uint32_t)(r * 144 + c8 * 16);
        #pragma unroll
        for (int sub = 0; sub < 3; ++sub) {
            int ct = c0 + sub;
            if (ct < nt) {
                size_t t0 = (bS + (size_t)ct * 64) * 128;
                cp16(kb + sub * TBYTES + so0,      gkh + t0 + (size_t)r * 128 + c8 * 16);
                cp16(kb + sub * TBYTES + so0 + 16, gkh + t0 + (size_t)r * 128 + c8 * 16 + 16);
            }
        }
    };

    // ldmatrix byte-offset helpers (within a tile)
    const uint32_t A_off = (uint32_t)(((lane & 15) * STR + ((lane >> 4) << 3)) * 2);
    const uint32_t B_off = (uint32_t)(((((lane >> 4) << 3) + (lane & 7)) * STR + (((lane >> 3) & 1) << 3)) * 2);

    const int g = lane >> 2, t = lane & 3;
    const int r0 = wy * 16 + g;
    const int gi0 = rt * 64 + r0, gi1 = gi0 + 8;
    const float sh0 = g_shift[bS + gi0];
    const float sh1 = g_shift[bS + gi1];
    float* attn_b = attn + (size_t)b * NS * NS;
    float* arow0 = attn_b + (size_t)gi0 * NS;
    float* arow1 = attn_b + (size_t)gi1 * NS;

    // ---------------- prologue: Q + phase0 chunks 0,1 ----------------
    {
        size_t q0 = (bS + (size_t)rt * 64) * 128;
        #pragma unroll
        for (int c = 0; c < 2; ++c) {
            int idx = tid * 2 + c, r = idx >> 3, c8 = idx & 7;
            cp16(sb + O_Q + (uint32_t)(r * 144 + c8 * 16),
                 gqh + q0 + (size_t)r * 128 + c8 * 16);
        }
        issue_k3(0, 0);
        CP_COMMIT();
        issue_k3(3, 1);
        CP_COMMIT();
    }
    CP_WAIT1();              // Q + chunk 0 complete
    __syncthreads();

    // --- Q fragments -> registers (loop-invariant, both phases) ---
    uint32_t aqf[4][4];
    {
        const uint32_t qo = sb + O_Q + A_off + (uint32_t)(wy * 16 * STR * 2);
        #pragma unroll
        for (int k = 0; k < 4; ++k) ldsm4(aqf[k], qo + (uint32_t)(k * 32));
    }

    // ============ PHASE 0: 1-term rowsum pass, 3 tiles per barrier ============
    float rs0 = 0.f, rs1 = 0.f;
    {
        int gidx = 0;
        for (int c0 = 0; c0 < nt; c0 += 3, ++gidx) {
            const uint32_t buf = (uint32_t)(gidx % 3);
            if (gidx) { CP_WAIT1(); __syncthreads(); }
            issue_k3(c0 + 6, (uint32_t)((gidx + 2) % 3));
            CP_COMMIT();

            const int ce = (c0 + 3 < nt) ? c0 + 3 : nt;
            for (int ct = c0; ct < ce; ++ct) {
                float sc[4][4] = {};
                const uint32_t khb = sb + O_B + buf * BUFB
                                   + (uint32_t)(ct - c0) * TBYTES
                                   + (uint32_t)(wx * 32 * STR * 2);
                #pragma unroll
                for (int k = 0; k < 4; ++k) {
                    uint32_t bh[4];
                    uint32_t kcol = (uint32_t)(k * 32);
                    #pragma unroll
                    for (int np = 0; np < 2; ++np) {
                        ldsm4(bh, khb + B_off + (uint32_t)(np * 16 * STR * 2) + kcol);
                        mma_f16(sc[2 * np],     aqf[k], bh[0], bh[1]);
                        mma_f16(sc[2 * np + 1], aqf[k], bh[2], bh[3]);
                    }
                }
                if (ct != rt) {
                    #pragma unroll
                    for (int nb = 0; nb < 4; ++nb) {
                        rs0 += exp2f(sc[nb][0] - sh0) + exp2f(sc[nb][1] - sh0);
                        rs1 += exp2f(sc[nb][2] - sh1) + exp2f(sc[nb][3] - sh1);
                    }
                } else {
                    const int gjb = ct * 64 + wx * 32 + 2 * t;
                    #pragma unroll
                    for (int nb = 0; nb < 4; ++nb) {
                        int gj = gjb + nb * 8;
                        if (gj < gi0)     rs0 += exp2f(sc[nb][0] - sh0);
                        if (gj + 1 < gi0) rs0 += exp2f(sc[nb][1] - sh0);
                        if (gj < gi1)     rs1 += exp2f(sc[nb][2] - sh1);
                        if (gj + 1 < gi1) rs1 += exp2f(sc[nb][3] - sh1);
                    }
                }
            }
        }
    }
    CP_WAIT0();
    __syncthreads();     // all phase-0 buffer reads done

    // --- issue phase-1 groups 0,1 NOW (overlaps the reduction below) ---
    issue_kv(0, 0);
    CP_COMMIT();
    if (nt > 1) issue_kv(1, 1);
    CP_COMMIT();

    // --- rowsum reduction (overlapped with cp.async above) ---
    rs0 += __shfl_xor_sync(0xffffffffu, rs0, 1);
    rs0 += __shfl_xor_sync(0xffffffffu, rs0, 2);
    rs1 += __shfl_xor_sync(0xffffffffu, rs1, 1);
    rs1 += __shfl_xor_sync(0xffffffffu, rs1, 2);
    if (t == 0) {
        rspart[wx][r0] = rs0;
        rspart[wx][r0 + 8] = rs1;
    }
    __syncthreads();
    if (tid < 64) {
        float rs = rspart[0][tid] + rspart[1][tid];
        inv_s[tid] = rs > 0.f ? 1.0f / rs : 0.f;
    }
    __syncthreads();
    const float inv0 = inv_s[r0];
    const float inv1 = inv_s[r0 + 8];

    // ================= PHASE 1: normalized write + AV =================
    float oc[8][4] = {};       // partial O[16 x 64] over this warp's j-half
    for (int ct = 0; ct < nt; ++ct) {
        const uint32_t buf = (uint32_t)(ct % 3);
        CP_WAIT1();
        __syncthreads();
        if (ct + 2 < nt) issue_kv(ct + 2, (uint32_t)((ct + 2) % 3));
        CP_COMMIT();

        // --- preload this warp's V fragments (rows wx*32.., 64 e-cols) ---
        uint32_t vfr0[4][4], vfr1[4][4];
        const uint32_t vhb = sb + O_B + buf * BUFB + 2 * TBYTES
                           + (uint32_t)(wx * 32 * STR * 2);
        #pragma unroll
        for (int ep = 0; ep < 4; ++ep)
            ldsm4t(vfr0[ep], vhb + A_off + (uint32_t)(ep * 32));

        // --- S[16x32] = Qs @ Kn^T (2-term, Q from registers) ---
        float sc[4][4] = {};
        const uint32_t khb = sb + O_B + buf * BUFB + (uint32_t)(wx * 32 * STR * 2);
        const uint32_t klb = khb + TBYTES;
        #pragma unroll
        for (int k = 0; k < 4; ++k) {
            uint32_t bh[4], bl[4];
            uint32_t kcol = (uint32_t)(k * 32);
            #pragma unroll
            for (int np = 0; np < 2; ++np) {
                uint32_t jo = (uint32_t)(np * 16 * STR * 2);
                ldsm4(bh, khb + B_off + jo + kcol);
                ldsm4(bl, klb + B_off + jo + kcol);
                mma_f16(sc[2 * np],     aqf[k], bh[0], bh[1]);
                mma_f16(sc[2 * np],     aqf[k], bl[0], bl[1]);
                mma_f16(sc[2 * np + 1], aqf[k], bh[2], bh[3]);
                mma_f16(sc[2 * np + 1], aqf[k], bl[2], bl[3]);
            }
        }
        #pragma unroll
        for (int ep = 0; ep < 4; ++ep)
            ldsm4t(vfr1[ep], vhb + A_off + (uint32_t)(16 * STR * 2) + (uint32_t)(ep * 32));

        // --- exp2 * inv (normalized) + attn store + fp16 A-frag repack ---
        uint32_t ah_[2][4];
        const int gjb = ct * 64 + wx * 32 + 2 * t;
        if (ct != rt) {
            #pragma unroll
            for (int nb = 0; nb < 4; ++nb) {
                int gj = gjb + nb * 8;
                float p00 = exp2f(sc[nb][0] - sh0) * inv0;
                float p01 = exp2f(sc[nb][1] - sh0) * inv0;
                float p10 = exp2f(sc[nb][2] - sh1) * inv1;
                float p11 = exp2f(sc[nb][3] - sh1) * inv1;
                *(float2*)(arow0 + gj) = make_float2(p00, p01);
                *(float2*)(arow1 + gj) = make_float2(p10, p11);
                int kb = nb >> 1, o = (nb & 1) * 2;
                ah_[kb][o]     = h2u(__floats2half2_rn(p00, p01));
                ah_[kb][o + 1] = h2u(__floats2half2_rn(p10, p11));
            }
        } else {
            #pragma unroll
            for (int nb = 0; nb < 4; ++nb) {
                int gj = gjb + nb * 8;
                float p00 = (gj < gi0)     ? exp2f(sc[nb][0] - sh0) * inv0 : 0.f;
                float p01 = (gj + 1 < gi0) ? exp2f(sc[nb][1] - sh0) * inv0 : 0.f;
                float p10 = (gj < gi1)     ? exp2f(sc[nb][2] - sh1) * inv1 : 0.f;
                float p11 = (gj + 1 < gi1) ? exp2f(sc[nb][3] - sh1) * inv1 : 0.f;
                *(float2*)(arow0 + gj) = make_float2(p00, p01);
                *(float2*)(arow1 + gj) = make_float2(p10, p11);
                int kb = nb >> 1, o = (nb & 1) * 2;
                ah_[kb][o]     = h2u(__floats2half2_rn(p00, p01));
                ah_[kb][o + 1] = h2u(__floats2half2_rn(p10, p11));
            }
        }

        // --- O += P_norm @ V ---
        #pragma unroll
        for (int ep = 0; ep < 4; ++ep) {
            mma_f16(oc[2 * ep],     ah_[0], vfr0[ep][0], vfr0[ep][1]);
            mma_f16(oc[2 * ep + 1], ah_[0], vfr0[ep][2], vfr0[ep][3]);
            mma_f16(oc[2 * ep],     ah_[1], vfr1[ep][0], vfr1[ep][1]);
            mma_f16(oc[2 * ep + 1], ah_[1], vfr1[ep][2], vfr1[ep][3]);
        }
    }
    __syncthreads();   // all loop reads done (KV region free for obuf)

    // ---- combine column-half O partials via padded smem buffer ----
    float* obuf = (float*)(smc + O_B);   // 64 x 66 floats
    if (wx == 1) {
        #pragma unroll
        for (int nb = 0; nb < 8; ++nb) {
            int c = nb * 8 + 2 * t;
            obuf[r0 * 66 + c]           = oc[nb][0];
            obuf[r0 * 66 + c + 1]       = oc[nb][1];
            obuf[(r0 + 8) * 66 + c]     = oc[nb][2];
            obuf[(r0 + 8) * 66 + c + 1] = oc[nb][3];
        }
    }
    __syncthreads();
    if (wx == 0) {
        float* o0 = out + (bS + gi0) * ND;
        float* o1 = out + (bS + gi1) * ND;
        if (gi0 == 0) {
            const float* vr = v + bS * ND;  // row 0: softmax over single -50000 diag
            #pragma unroll
            for (int nb = 0; nb < 8; ++nb) {
                int c = nb * 8 + 2 * t;
                *(float2*)(o0 + c) = *(const float2*)(vr + c);
            }
        } else {
            #pragma unroll
            for (int nb = 0; nb < 8; ++nb) {
                int c = nb * 8 + 2 * t;
                *(float2*)(o0 + c) = make_float2(oc[nb][0] + obuf[r0 * 66 + c],
                                                 oc[nb][1] + obuf[r0 * 66 + c + 1]);
            }
        }
        #pragma unroll
        for (int nb = 0; nb < 8; ++nb) {
            int c = nb * 8 + 2 * t;
            *(float2*)(o1 + c) = make_float2(oc[nb][2] + obuf[(r0 + 8) * 66 + c],
                                             oc[nb][3] + obuf[(r0 + 8) * 66 + c + 1]);
        }
    }

    // ---- upper-triangle zero-fill (anti-correlated with compute) ----
    {
        int r = tid >> 2;
        float* rowp = attn_b + (size_t)(rt * 64 + r) * NS;
        float4 z = make_float4(0.f, 0.f, 0.f, 0.f);
        for (int c = nt * 64 + (tid & 3) * 4; c < NS; c += 16)
            *(float4*)(rowp + c) = z;
    }
    if (rt == 0 && tid == 0) attn_b[0] = 1.0f;  // row 0: softmax over single diag entry
}

// ---------------------------------------------------------------------------
extern "C" void kernel_launch(void* const* d_in, const int* in_sizes, int n_in,
                              void* d_out, int out_size) {
    const float* qk = (const float*)d_in[0];
    const float* v  = (const float*)d_in[1];
    float* out  = (float*)d_out;
    float* attn = out + (size_t)NB * NS * ND;

    cudaFuncSetAttribute(attn_main, cudaFuncAttributeMaxDynamicSharedMemorySize, SMEM_SZ);
    prep_kernel<<<NB * NS / 8, 256>>>(qk, v);
    attn_main<<<256, 256, SMEM_SZ>>>(v, out, attn);
}

// round 16
// speedup vs baseline: 1.6300x; 1.1856x over previous
#include <cuda_runtime.h>
#include <cuda_fp16.h>
#include <cstdint>

#define NB 4
#define NS 4096
#define ND 64
#define SCALE2 0.18033688f   // 0.125 * log2(e): exp(x*0.125) = exp2(x*SCALE2)
#define STR 72u              // fp16 elems per smem row (144 B -> LDSM conflict-free)
#define TBYTES 9216u         // one 64x72 fp16 tile
#define BUFB 27648u          // buffer group stride: 3 KH tiles (ph0) / KH+VH (ph1)

// dynamic smem: [Q 9216][3 x BUFB]
#define O_Q 0u
#define O_B 9216u
#define SMEM_SZ 92160u

// pre-split fp16 operand arrays (uint32 = fp16x2), rows of 128 B
__device__ __align__(128) uint32_t g_qh[(size_t)NB * NS * 32];  // fp16(q*SCALE2)
__device__ __align__(128) uint32_t g_kh[(size_t)NB * NS * 32];  // fp16(kn)
__device__ __align__(128) uint32_t g_vh[(size_t)NB * NS * 32];  // fp16(v)
__device__ float g_shift[NB * NS];

// ------------------------------------------------------------- PTX helpers
__device__ __forceinline__ uint32_t smem_u32(const void* p) {
    uint32_t a;
    asm("{ .reg .u64 t; cvta.to.shared.u64 t, %1; cvt.u32.u64 %0, t; }" : "=r"(a) : "l"(p));
    return a;
}
__device__ __forceinline__ uint64_t gaddr(const void* p) {
    uint64_t a;
    asm("cvta.to.global.u64 %0, %1;" : "=l"(a) : "l"(p));
    return a;
}
__device__ __forceinline__ void cp16(uint32_t dst, uint64_t src) {
    asm volatile("cp.async.cg.shared.global [%0], [%1], 16;" ::"r"(dst), "l"(src));
}
#define CP_COMMIT() asm volatile("cp.async.commit_group;" ::: "memory")
#define CP_WAIT1()  asm volatile("cp.async.wait_group 1;" ::: "memory")
#define CP_WAIT0()  asm volatile("cp.async.wait_group 0;" ::: "memory")

__device__ __forceinline__ void ldsm4(uint32_t* d, uint32_t a) {
    asm volatile("ldmatrix.sync.aligned.m8n8.x4.shared.b16 {%0,%1,%2,%3}, [%4];"
                 : "=r"(d[0]), "=r"(d[1]), "=r"(d[2]), "=r"(d[3]) : "r"(a));
}
__device__ __forceinline__ void ldsm4t(uint32_t* d, uint32_t a) {
    asm volatile("ldmatrix.sync.aligned.m8n8.x4.trans.shared.b16 {%0,%1,%2,%3}, [%4];"
                 : "=r"(d[0]), "=r"(d[1]), "=r"(d[2]), "=r"(d[3]) : "r"(a));
}
__device__ __forceinline__ void mma_f16(float* c, const uint32_t* a, uint32_t b0, uint32_t b1) {
    asm volatile("mma.sync.aligned.m16n8k16.row.col.f32.f16.f16.f32 "
                 "{%0,%1,%2,%3}, {%4,%5,%6,%7}, {%8,%9}, {%0,%1,%2,%3};"
                 : "+f"(c[0]), "+f"(c[1]), "+f"(c[2]), "+f"(c[3])
                 : "r"(a[0]), "r"(a[1]), "r"(a[2]), "r"(a[3]), "r"(b0), "r"(b1));
}
__device__ __forceinline__ uint32_t h2u(__half2 h) { return *reinterpret_cast<uint32_t*>(&h); }

// ---------------------------------------------------------------------------
// Kernel 1: norms -> shift (log2-domain); fp16 Q*SCALE2, fp16 Kn, fp16 V.
// ---------------------------------------------------------------------------
__global__ void prep_kernel(const float* __restrict__ qk, const float* __restrict__ v) {
    int row = blockIdx.x * 8 + (threadIdx.x >> 5);
    int lane = threadIdx.x & 31;
    float2 q = *(const float2*)(qk + (size_t)row * ND + lane * 2);
    float ss = q.x * q.x + q.y * q.y;
    #pragma unroll
    for (int o = 16; o >= 1; o >>= 1) ss += __shfl_xor_sync(0xffffffffu, ss, o);
    float nrm = fmaxf(sqrtf(ss), 1e-12f);
    float inv = 1.0f / nrm;
    size_t w = (size_t)row * 32 + lane;
    g_qh[w] = h2u(__floats2half2_rn(q.x * SCALE2, q.y * SCALE2));
    g_kh[w] = h2u(__floats2half2_rn(q.x * inv, q.y * inv));
    float2 vv = *(const float2*)(v + (size_t)row * ND + lane * 2);
    g_vh[w] = h2u(__floats2half2_rn(vv.x, vv.y));
    if (lane == 0) g_shift[row] = nrm * SCALE2;
}

// ---------------------------------------------------------------------------
// Kernel 2: fused attention (64-row strips, 256 CTAs, 8 warps).
// Phase 0: 1-term S, KH-only, 3 tiles/buffer-group -> rowsum.
// Phase 1: 1-term S -> exp2 -> NORMALIZED attn -> AV (1-term) -> out.
// Diagonal tile specialized; phase transition overlapped with prefetch.
// ---------------------------------------------------------------------------
__global__ __launch_bounds__(256, 2)
void attn_main(const float* __restrict__ v,
               float* __restrict__ out, float* __restrict__ attn)
{
    extern __shared__ char smc[];
    const uint32_t sb = smem_u32(smc);
    const int tid = threadIdx.x, lane = tid & 31, w = tid >> 5;
    const int wy = w & 3, wx = w >> 2;   // row group (16 rows), col half (32 j-cols)

    // balanced schedule: paired SMs sum to 65 tile-iters
    int l = blockIdx.x, rt, b;
    if (l < 40)       { rt = 63 - (l >> 2); b = l & 3; }
    else if (l < 148) { int i = l - 40; rt = 53 - (i >> 2); b = i & 3; }
    else              { int i = l - 148; rt = i >> 2; b = i & 3; }
    const size_t bS = (size_t)b * NS;
    const int nt = rt + 1;

    __shared__ float rspart[2][64];
    __shared__ float inv_s[64];

    const uint64_t gqh = gaddr(g_qh);
    const uint64_t gkh = gaddr(g_kh);
    const uint64_t gvh = gaddr(g_vh);

    auto issue_kv = [&](int ct, uint32_t buf) {   // KH + VH group (phase 1)
        size_t t0 = (bS + (size_t)ct * 64) * 128;
        uint32_t kb = sb + O_B + buf * BUFB;
        #pragma unroll
        for (int c = 0; c < 2; ++c) {
            int idx = tid * 2 + c, r = idx >> 3, c8 = idx & 7;
            uint32_t so = (uint32_t)(r * 144 + c8 * 16);
            uint64_t go = t0 + (size_t)r * 128 + c8 * 16;
            cp16(kb + so, gkh + go);
            cp16(kb + TBYTES + so, gvh + go);
        }
    };
    auto issue_k3 = [&](int c0, uint32_t buf) {   // 3 KH tiles (phase 0)
        uint32_t kb = sb + O_B + buf * BUFB;
        int idx0 = tid * 2, r = idx0 >> 3, c8 = idx0 & 7;
        uint32_t so0 = (uint32_t)(r * 144 + c8 * 16);
        #pragma unroll
        for (int sub = 0; sub < 3; ++sub) {
            int ct = c0 + sub;
            if (ct < nt) {
                size_t t0 = (bS + (size_t)ct * 64) * 128;
                cp16(kb + sub * TBYTES + so0,      gkh + t0 + (size_t)r * 128 + c8 * 16);
                cp16(kb + sub * TBYTES + so0 + 16, gkh + t0 + (size_t)r * 128 + c8 * 16 + 16);
            }
        }
    };

    // ldmatrix byte-offset helpers (within a tile)
    const uint32_t A_off = (uint32_t)(((lane & 15) * STR + ((lane >> 4) << 3)) * 2);
    const uint32_t B_off = (uint32_t)(((((lane >> 4) << 3) + (lane & 7)) * STR + (((lane >> 3) & 1) << 3)) * 2);

    const int g = lane >> 2, t = lane & 3;
    const int r0 = wy * 16 + g;
    const int gi0 = rt * 64 + r0, gi1 = gi0 + 8;
    const float sh0 = g_shift[bS + gi0];
    const float sh1 = g_shift[bS + gi1];
    float* attn_b = attn + (size_t)b * NS * NS;
    float* arow0 = attn_b + (size_t)gi0 * NS;
    float* arow1 = attn_b + (size_t)gi1 * NS;

    // ---------------- prologue: Q + phase0 chunks 0,1 ----------------
    {
        size_t q0 = (bS + (size_t)rt * 64) * 128;
        #pragma unroll
        for (int c = 0; c < 2; ++c) {
            int idx = tid * 2 + c, r = idx >> 3, c8 = idx & 7;
            cp16(sb + O_Q + (uint32_t)(r * 144 + c8 * 16),
                 gqh + q0 + (size_t)r * 128 + c8 * 16);
        }
        issue_k3(0, 0);
        CP_COMMIT();
        issue_k3(3, 1);
        CP_COMMIT();
    }
    CP_WAIT1();              // Q + chunk 0 complete
    __syncthreads();

    // --- Q fragments -> registers (loop-invariant, both phases) ---
    uint32_t aqf[4][4];
    {
        const uint32_t qo = sb + O_Q + A_off + (uint32_t)(wy * 16 * STR * 2);
        #pragma unroll
        for (int k = 0; k < 4; ++k) ldsm4(aqf[k], qo + (uint32_t)(k * 32));
    }

    // ============ PHASE 0: 1-term rowsum pass, 3 tiles per barrier ============
    float rs0 = 0.f, rs1 = 0.f;
    {
        int gidx = 0;
        for (int c0 = 0; c0 < nt; c0 += 3, ++gidx) {
            const uint32_t buf = (uint32_t)(gidx % 3);
            if (gidx) { CP_WAIT1(); __syncthreads(); }
            issue_k3(c0 + 6, (uint32_t)((gidx + 2) % 3));
            CP_COMMIT();

            const int ce = (c0 + 3 < nt) ? c0 + 3 : nt;
            for (int ct = c0; ct < ce; ++ct) {
                float sc[4][4] = {};
                const uint32_t khb = sb + O_B + buf * BUFB
                                   + (uint32_t)(ct - c0) * TBYTES
                                   + (uint32_t)(wx * 32 * STR * 2);
                #pragma unroll
                for (int k = 0; k < 4; ++k) {
                    uint32_t bh[4];
                    uint32_t kcol = (uint32_t)(k * 32);
                    #pragma unroll
                    for (int np = 0; np < 2; ++np) {
                        ldsm4(bh, khb + B_off + (uint32_t)(np * 16 * STR * 2) + kcol);
                        mma_f16(sc[2 * np],     aqf[k], bh[0], bh[1]);
                        mma_f16(sc[2 * np + 1], aqf[k], bh[2], bh[3]);
                    }
                }
                if (ct != rt) {
                    #pragma unroll
                    for (int nb = 0; nb < 4; ++nb) {
                        rs0 += exp2f(sc[nb][0] - sh0) + exp2f(sc[nb][1] - sh0);
                        rs1 += exp2f(sc[nb][2] - sh1) + exp2f(sc[nb][3] - sh1);
                    }
                } else {
                    const int gjb = ct * 64 + wx * 32 + 2 * t;
                    #pragma unroll
                    for (int nb = 0; nb < 4; ++nb) {
                        int gj = gjb + nb * 8;
                        if (gj < gi0)     rs0 += exp2f(sc[nb][0] - sh0);
                        if (gj + 1 < gi0) rs0 += exp2f(sc[nb][1] - sh0);
                        if (gj < gi1)     rs1 += exp2f(sc[nb][2] - sh1);
                        if (gj + 1 < gi1) rs1 += exp2f(sc[nb][3] - sh1);
                    }
                }
            }
        }
    }
    CP_WAIT0();
    __syncthreads();     // all phase-0 buffer reads done

    // --- issue phase-1 groups 0,1 NOW (overlaps the reduction below) ---
    issue_kv(0, 0);
    CP_COMMIT();
    if (nt > 1) issue_kv(1, 1);
    CP_COMMIT();

    // --- rowsum reduction (overlapped with cp.async above) ---
    rs0 += __shfl_xor_sync(0xffffffffu, rs0, 1);
    rs0 += __shfl_xor_sync(0xffffffffu, rs0, 2);
    rs1 += __shfl_xor_sync(0xffffffffu, rs1, 1);
    rs1 += __shfl_xor_sync(0xffffffffu, rs1, 2);
    if (t == 0) {
        rspart[wx][r0] = rs0;
        rspart[wx][r0 + 8] = rs1;
    }
    __syncthreads();
    if (tid < 64) {
        float rs = rspart[0][tid] + rspart[1][tid];
        inv_s[tid] = rs > 0.f ? 1.0f / rs : 0.f;
    }
    __syncthreads();
    const float inv0 = inv_s[r0];
    const float inv1 = inv_s[r0 + 8];

    // ================= PHASE 1: normalized write + AV =================
    float oc[8][4] = {};       // partial O[16 x 64] over this warp's j-half
    for (int ct = 0; ct < nt; ++ct) {
        const uint32_t buf = (uint32_t)(ct % 3);
        CP_WAIT1();
        __syncthreads();
        if (ct + 2 < nt) issue_kv(ct + 2, (uint32_t)((ct + 2) % 3));
        CP_COMMIT();

        // --- preload this warp's V fragments (rows wx*32.., 64 e-cols) ---
        uint32_t vfr0[4][4], vfr1[4][4];
        const uint32_t vhb = sb + O_B + buf * BUFB + TBYTES
                           + (uint32_t)(wx * 32 * STR * 2);
        #pragma unroll
        for (int ep = 0; ep < 4; ++ep)
            ldsm4t(vfr0[ep], vhb + A_off + (uint32_t)(ep * 32));

        // --- S[16x32] = Qs @ Kn^T (1-term, Q from registers) ---
        float sc[4][4] = {};
        const uint32_t khb = sb + O_B + buf * BUFB + (uint32_t)(wx * 32 * STR * 2);
        #pragma unroll
        for (int k = 0; k < 4; ++k) {
            uint32_t bh[4];
            uint32_t kcol = (uint32_t)(k * 32);
            #pragma unroll
            for (int np = 0; np < 2; ++np) {
                ldsm4(bh, khb + B_off + (uint32_t)(np * 16 * STR * 2) + kcol);
                mma_f16(sc[2 * np],     aqf[k], bh[0], bh[1]);
                mma_f16(sc[2 * np + 1], aqf[k], bh[2], bh[3]);
            }
        }
        #pragma unroll
        for (int ep = 0; ep < 4; ++ep)
            ldsm4t(vfr1[ep], vhb + A_off + (uint32_t)(16 * STR * 2) + (uint32_t)(ep * 32));

        // --- exp2 * inv (normalized) + attn store + fp16 A-frag repack ---
        uint32_t ah_[2][4];
        const int gjb = ct * 64 + wx * 32 + 2 * t;
        if (ct != rt) {
            #pragma unroll
            for (int nb = 0; nb < 4; ++nb) {
                int gj = gjb + nb * 8;
                float p00 = exp2f(sc[nb][0] - sh0) * inv0;
                float p01 = exp2f(sc[nb][1] - sh0) * inv0;
                float p10 = exp2f(sc[nb][2] - sh1) * inv1;
                float p11 = exp2f(sc[nb][3] - sh1) * inv1;
                *(float2*)(arow0 + gj) = make_float2(p00, p01);
                *(float2*)(arow1 + gj) = make_float2(p10, p11);
                int kb = nb >> 1, o = (nb & 1) * 2;
                ah_[kb][o]     = h2u(__floats2half2_rn(p00, p01));
                ah_[kb][o + 1] = h2u(__floats2half2_rn(p10, p11));
            }
        } else {
            #pragma unroll
            for (int nb = 0; nb < 4; ++nb) {
                int gj = gjb + nb * 8;
                float p00 = (gj < gi0)     ? exp2f(sc[nb][0] - sh0) * inv0 : 0.f;
                float p01 = (gj + 1 < gi0) ? exp2f(sc[nb][1] - sh0) * inv0 : 0.f;
                float p10 = (gj < gi1)     ? exp2f(sc[nb][2] - sh1) * inv1 : 0.f;
                float p11 = (gj + 1 < gi1) ? exp2f(sc[nb][3] - sh1) * inv1 : 0.f;
                *(float2*)(arow0 + gj) = make_float2(p00, p01);
                *(float2*)(arow1 + gj) = make_float2(p10, p11);
                int kb = nb >> 1, o = (nb & 1) * 2;
                ah_[kb][o]     = h2u(__floats2half2_rn(p00, p01));
                ah_[kb][o + 1] = h2u(__floats2half2_rn(p10, p11));
            }
        }

        // --- O += P_norm @ V ---
        #pragma unroll
        for (int ep = 0; ep < 4; ++ep) {
            mma_f16(oc[2 * ep],     ah_[0], vfr0[ep][0], vfr0[ep][1]);
            mma_f16(oc[2 * ep + 1], ah_[0], vfr0[ep][2], vfr0[ep][3]);
            mma_f16(oc[2 * ep],     ah_[1], vfr1[ep][0], vfr1[ep][1]);
            mma_f16(oc[2 * ep + 1], ah_[1], vfr1[ep][2], vfr1[ep][3]);
        }
    }
    __syncthreads();   // all loop reads done (KV region free for obuf)

    // ---- combine column-half O partials via padded smem buffer ----
    float* obuf = (float*)(smc + O_B);   // 64 x 66 floats
    if (wx == 1) {
        #pragma unroll
        for (int nb = 0; nb < 8; ++nb) {
            int c = nb * 8 + 2 * t;
            obuf[r0 * 66 + c]           = oc[nb][0];
            obuf[r0 * 66 + c + 1]       = oc[nb][1];
            obuf[(r0 + 8) * 66 + c]     = oc[nb][2];
            obuf[(r0 + 8) * 66 + c + 1] = oc[nb][3];
        }
    }
    __syncthreads();
    if (wx == 0) {
        float* o0 = out + (bS + gi0) * ND;
        float* o1 = out + (bS + gi1) * ND;
        if (gi0 == 0) {
            const float* vr = v + bS * ND;  // row 0: softmax over single -50000 diag
            #pragma unroll
            for (int nb = 0; nb < 8; ++nb) {
                int c = nb * 8 + 2 * t;
                *(float2*)(o0 + c) = *(const float2*)(vr + c);
            }
        } else {
            #pragma unroll
            for (int nb = 0; nb < 8; ++nb) {
                int c = nb * 8 + 2 * t;
                *(float2*)(o0 + c) = make_float2(oc[nb][0] + obuf[r0 * 66 + c],
                                                 oc[nb][1] + obuf[r0 * 66 + c + 1]);
            }
        }
        #pragma unroll
        for (int nb = 0; nb < 8; ++nb) {
            int c = nb * 8 + 2 * t;
            *(float2*)(o1 + c) = make_float2(oc[nb][2] + obuf[(r0 + 8) * 66 + c],
                                             oc[nb][3] + obuf[(r0 + 8) * 66 + c + 1]);
        }
    }

    // ---- upper-triangle zero-fill (anti-correlated with compute) ----
    {
        int r = tid >> 2;
        float* rowp = attn_b + (size_t)(rt * 64 + r) * NS;
        float4 z = make_float4(0.f, 0.f, 0.f, 0.f);
        for (int c = nt * 64 + (tid & 3) * 4; c < NS; c += 16)
            *(float4*)(rowp + c) = z;
    }
    if (rt == 0 && tid == 0) attn_b[0] = 1.0f;  // row 0: softmax over single diag entry
}

// ---------------------------------------------------------------------------
extern "C" void kernel_launch(void* const* d_in, const int* in_sizes, int n_in,
                              void* d_out, int out_size) {
    const float* qk = (const float*)d_in[0];
    const float* v  = (const float*)d_in[1];
    float* out  = (float*)d_out;
    float* attn = out + (size_t)NB * NS * ND;

    cudaFuncSetAttribute(attn_main, cudaFuncAttributeMaxDynamicSharedMemorySize, SMEM_SZ);
    prep_kernel<<<NB * NS / 8, 256>>>(qk, v);
    attn_main<<<256, 256, SMEM_SZ>>>(v, out, attn);
}

// round 17
// speedup vs baseline: 1.6981x; 1.0418x over previous
#include <cuda_runtime.h>
#include <cuda_fp16.h>
#include <cstdint>

#define NB 4
#define NS 4096
#define ND 64
#define SCALE2 0.18033688f   // 0.125 * log2(e): exp(x*0.125) = exp2(x*SCALE2)
#define STR 72u              // fp16 elems per smem row (144 B -> LDSM conflict-free)
#define TBYTES 9216u         // one 64x72 fp16 tile
#define BUFB 27648u          // buffer group stride: 3 KH tiles (ph0) / KH+VH (ph1)

// dynamic smem: [Q 9216][3 x BUFB]
#define O_Q 0u
#define O_B 9216u
#define SMEM_SZ 92160u

// pre-split fp16 operand arrays (uint32 = fp16x2), rows of 128 B
__device__ __align__(128) uint32_t g_qh[(size_t)NB * NS * 32];  // fp16(q*SCALE2)
__device__ __align__(128) uint32_t g_kh[(size_t)NB * NS * 32];  // fp16(kn)
__device__ __align__(128) uint32_t g_vh[(size_t)NB * NS * 32];  // fp16(v)
__device__ float g_shift[NB * NS];

// ------------------------------------------------------------- PTX helpers
__device__ __forceinline__ uint32_t smem_u32(const void* p) {
    uint32_t a;
    asm("{ .reg .u64 t; cvta.to.shared.u64 t, %1; cvt.u32.u64 %0, t; }" : "=r"(a) : "l"(p));
    return a;
}
__device__ __forceinline__ uint64_t gaddr(const void* p) {
    uint64_t a;
    asm("cvta.to.global.u64 %0, %1;" : "=l"(a) : "l"(p));
    return a;
}
__device__ __forceinline__ void cp16(uint32_t dst, uint64_t src) {
    asm volatile("cp.async.cg.shared.global [%0], [%1], 16;" ::"r"(dst), "l"(src));
}
#define CP_COMMIT() asm volatile("cp.async.commit_group;" ::: "memory")
#define CP_WAIT1()  asm volatile("cp.async.wait_group 1;" ::: "memory")
#define CP_WAIT0()  asm volatile("cp.async.wait_group 0;" ::: "memory")

__device__ __forceinline__ void ldsm4(uint32_t* d, uint32_t a) {
    asm volatile("ldmatrix.sync.aligned.m8n8.x4.shared.b16 {%0,%1,%2,%3}, [%4];"
                 : "=r"(d[0]), "=r"(d[1]), "=r"(d[2]), "=r"(d[3]) : "r"(a));
}
__device__ __forceinline__ void ldsm4t(uint32_t* d, uint32_t a) {
    asm volatile("ldmatrix.sync.aligned.m8n8.x4.trans.shared.b16 {%0,%1,%2,%3}, [%4];"
                 : "=r"(d[0]), "=r"(d[1]), "=r"(d[2]), "=r"(d[3]) : "r"(a));
}
__device__ __forceinline__ void mma_f16(float* c, const uint32_t* a, uint32_t b0, uint32_t b1) {
    asm volatile("mma.sync.aligned.m16n8k16.row.col.f32.f16.f16.f32 "
                 "{%0,%1,%2,%3}, {%4,%5,%6,%7}, {%8,%9}, {%0,%1,%2,%3};"
                 : "+f"(c[0]), "+f"(c[1]), "+f"(c[2]), "+f"(c[3])
                 : "r"(a[0]), "r"(a[1]), "r"(a[2]), "r"(a[3]), "r"(b0), "r"(b1));
}
__device__ __forceinline__ uint32_t h2u(__half2 h) { return *reinterpret_cast<uint32_t*>(&h); }
__device__ __forceinline__ float2 ex2_f16x2(float a, float b) {
    __half2 h = __floats2half2_rn(a, b);
    uint32_t r;
    asm("ex2.approx.f16x2 %0, %1;" : "=r"(r) : "r"(h2u(h)));
    return __half22float2(*reinterpret_cast<__half2*>(&r));
}

// ---------------------------------------------------------------------------
// Kernel 1: norms -> shift (log2-domain); fp16 Q*SCALE2, fp16 Kn, fp16 V.
// ---------------------------------------------------------------------------
__global__ void prep_kernel(const float* __restrict__ qk, const float* __restrict__ v) {
    int row = blockIdx.x * 8 + (threadIdx.x >> 5);
    int lane = threadIdx.x & 31;
    float2 q = *(const float2*)(qk + (size_t)row * ND + lane * 2);
    float ss = q.x * q.x + q.y * q.y;
    #pragma unroll
    for (int o = 16; o >= 1; o >>= 1) ss += __shfl_xor_sync(0xffffffffu, ss, o);
    float nrm = fmaxf(sqrtf(ss), 1e-12f);
    float inv = 1.0f / nrm;
    size_t w = (size_t)row * 32 + lane;
    g_qh[w] = h2u(__floats2half2_rn(q.x * SCALE2, q.y * SCALE2));
    g_kh[w] = h2u(__floats2half2_rn(q.x * inv, q.y * inv));
    float2 vv = *(const float2*)(v + (size_t)row * ND + lane * 2);
    g_vh[w] = h2u(__floats2half2_rn(vv.x, vv.y));
    if (lane == 0) g_shift[row] = nrm * SCALE2;
}

// ---------------------------------------------------------------------------
// Kernel 2: fused attention (64-row strips, 256 CTAs, 8 warps).
// Phase 0: 1-term S, KH-only, 3 tiles/chunk; exp via ex2.approx.f16x2.
// Phase 1: 1-term S -> exp2(s - shp) [shp folds 1/rowsum] -> attn -> AV -> out.
// ---------------------------------------------------------------------------
__global__ __launch_bounds__(256, 2)
void attn_main(const float* __restrict__ v,
               float* __restrict__ out, float* __restrict__ attn)
{
    extern __shared__ char smc[];
    const uint32_t sb = smem_u32(smc);
    const int tid = threadIdx.x, lane = tid & 31, w = tid >> 5;
    const int wy = w & 3, wx = w >> 2;   // row group (16 rows), col half (32 j-cols)

    // balanced schedule: paired SMs sum to 65 tile-iters
    int l = blockIdx.x, rt, b;
    if (l < 40)       { rt = 63 - (l >> 2); b = l & 3; }
    else if (l < 148) { int i = l - 40; rt = 53 - (i >> 2); b = i & 3; }
    else              { int i = l - 148; rt = i >> 2; b = i & 3; }
    const size_t bS = (size_t)b * NS;
    const int nt = rt + 1;

    __shared__ float rspart[2][64];
    __shared__ float shp_s[64];     // sh + log2(rowsum): normalize folded into shift

    const uint64_t gqh = gaddr(g_qh);
    const uint64_t gkh = gaddr(g_kh);
    const uint64_t gvh = gaddr(g_vh);

    auto issue_kv = [&](int ct, uint32_t buf) {   // KH + VH group (phase 1)
        size_t t0 = (bS + (size_t)ct * 64) * 128;
        uint32_t kb = sb + O_B + buf * BUFB;
        #pragma unroll
        for (int c = 0; c < 2; ++c) {
            int idx = tid * 2 + c, r = idx >> 3, c8 = idx & 7;
            uint32_t so = (uint32_t)(r * 144 + c8 * 16);
            uint64_t go = t0 + (size_t)r * 128 + c8 * 16;
            cp16(kb + so, gkh + go);
            cp16(kb + TBYTES + so, gvh + go);
        }
    };
    auto issue_k3 = [&](int c0, uint32_t buf) {   // 3 KH tiles (phase 0)
        uint32_t kb = sb + O_B + buf * BUFB;
        int idx0 = tid * 2, r = idx0 >> 3, c8 = idx0 & 7;
        uint32_t so0 = (uint32_t)(r * 144 + c8 * 16);
        #pragma unroll
        for (int sub = 0; sub < 3; ++sub) {
            int ct = c0 + sub;
            if (ct < nt) {
                size_t t0 = (bS + (size_t)ct * 64) * 128;
                cp16(kb + sub * TBYTES + so0,      gkh + t0 + (size_t)r * 128 + c8 * 16);
                cp16(kb + sub * TBYTES + so0 + 16, gkh + t0 + (size_t)r * 128 + c8 * 16 + 16);
            }
        }
    };

    // ldmatrix byte-offset helpers (within a tile)
    const uint32_t A_off = (uint32_t)(((lane & 15) * STR + ((lane >> 4) << 3)) * 2);
    const uint32_t B_off = (uint32_t)(((((lane >> 4) << 3) + (lane & 7)) * STR + (((lane >> 3) & 1) << 3)) * 2);

    const int g = lane >> 2, t = lane & 3;
    const int r0 = wy * 16 + g;
    const int gi0 = rt * 64 + r0, gi1 = gi0 + 8;
    const float sh0 = g_shift[bS + gi0];
    const float sh1 = g_shift[bS + gi1];
    float* attn_b = attn + (size_t)b * NS * NS;
    float* arow0 = attn_b + (size_t)gi0 * NS;
    float* arow1 = attn_b + (size_t)gi1 * NS;

    // ---------------- prologue: Q + phase0 chunks 0,1 ----------------
    {
        size_t q0 = (bS + (size_t)rt * 64) * 128;
        #pragma unroll
        for (int c = 0; c < 2; ++c) {
            int idx = tid * 2 + c, r = idx >> 3, c8 = idx & 7;
            cp16(sb + O_Q + (uint32_t)(r * 144 + c8 * 16),
                 gqh + q0 + (size_t)r * 128 + c8 * 16);
        }
        issue_k3(0, 0);
        CP_COMMIT();
        issue_k3(3, 1);
        CP_COMMIT();
    }
    CP_WAIT1();              // Q + chunk 0 complete
    __syncthreads();

    // --- Q fragments -> registers (loop-invariant, both phases) ---
    uint32_t aqf[4][4];
    {
        const uint32_t qo = sb + O_Q + A_off + (uint32_t)(wy * 16 * STR * 2);
        #pragma unroll
        for (int k = 0; k < 4; ++k) ldsm4(aqf[k], qo + (uint32_t)(k * 32));
    }

    // ============ PHASE 0: 1-term rowsum pass, 3 tiles per barrier ============
    float rs0 = 0.f, rs1 = 0.f;
    {
        int gidx = 0;
        for (int c0 = 0; c0 < nt; c0 += 3, ++gidx) {
            const uint32_t buf = (uint32_t)(gidx % 3);
            if (gidx) { CP_WAIT1(); __syncthreads(); }
            issue_k3(c0 + 6, (uint32_t)((gidx + 2) % 3));
            CP_COMMIT();

            const int ce = (c0 + 3 < nt) ? c0 + 3 : nt;
            for (int ct = c0; ct < ce; ++ct) {
                float sc[4][4] = {};
                const uint32_t khb = sb + O_B + buf * BUFB
                                   + (uint32_t)(ct - c0) * TBYTES
                                   + (uint32_t)(wx * 32 * STR * 2);
                #pragma unroll
                for (int k = 0; k < 4; ++k) {
                    uint32_t bh[4];
                    uint32_t kcol = (uint32_t)(k * 32);
                    #pragma unroll
                    for (int np = 0; np < 2; ++np) {
                        ldsm4(bh, khb + B_off + (uint32_t)(np * 16 * STR * 2) + kcol);
                        mma_f16(sc[2 * np],     aqf[k], bh[0], bh[1]);
                        mma_f16(sc[2 * np + 1], aqf[k], bh[2], bh[3]);
                    }
                }
                if (ct != rt) {
                    // fp16x2 exp: one MUFU per two values; rowsum averaging
                    // washes out the per-term fp16 rounding (~1e-3/sqrt(n)).
                    #pragma unroll
                    for (int nb = 0; nb < 4; ++nb) {
                        float2 e0 = ex2_f16x2(sc[nb][0] - sh0, sc[nb][1] - sh0);
                        float2 e1 = ex2_f16x2(sc[nb][2] - sh1, sc[nb][3] - sh1);
                        rs0 += e0.x + e0.y;
                        rs1 += e1.x + e1.y;
                    }
                } else {
                    const int gjb = ct * 64 + wx * 32 + 2 * t;
                    #pragma unroll
                    for (int nb = 0; nb < 4; ++nb) {
                        int gj = gjb + nb * 8;
                        if (gj < gi0)     rs0 += exp2f(sc[nb][0] - sh0);
                        if (gj + 1 < gi0) rs0 += exp2f(sc[nb][1] - sh0);
                        if (gj < gi1)     rs1 += exp2f(sc[nb][2] - sh1);
                        if (gj + 1 < gi1) rs1 += exp2f(sc[nb][3] - sh1);
                    }
                }
            }
        }
    }
    CP_WAIT0();
    __syncthreads();     // all phase-0 buffer reads done

    // --- issue phase-1 groups 0,1 NOW (overlaps the reduction below) ---
    issue_kv(0, 0);
    CP_COMMIT();
    if (nt > 1) issue_kv(1, 1);
    CP_COMMIT();

    // --- rowsum reduction; fold 1/rs into the shift: shp = sh + log2(rs) ---
    rs0 += __shfl_xor_sync(0xffffffffu, rs0, 1);
    rs0 += __shfl_xor_sync(0xffffffffu, rs0, 2);
    rs1 += __shfl_xor_sync(0xffffffffu, rs1, 1);
    rs1 += __shfl_xor_sync(0xffffffffu, rs1, 2);
    if (t == 0) {
        rspart[wx][r0] = rs0;
        rspart[wx][r0 + 8] = rs1;
    }
    __syncthreads();
    if (tid < 64) {
        float rs = rspart[0][tid] + rspart[1][tid];
        // rs==0 only for global row 0 (fully masked): log2f(0) = -inf, and the
        // diag-tile masked path selects 0 for every row-0 element, so the inf
        // from exp2(s+inf) is never stored.
        shp_s[tid] = g_shift[bS + rt * 64 + tid] + __log2f(rs);
    }
    __syncthreads();
    const float shp0 = shp_s[r0];
    const float shp1 = shp_s[r0 + 8];

    // ================= PHASE 1: normalized write + AV =================
    float oc[8][4] = {};       // partial O[16 x 64] over this warp's j-half
    for (int ct = 0; ct < nt; ++ct) {
        const uint32_t buf = (uint32_t)(ct % 3);
        CP_WAIT1();
        __syncthreads();
        if (ct + 2 < nt) issue_kv(ct + 2, (uint32_t)((ct + 2) % 3));
        CP_COMMIT();

        // --- preload this warp's V fragments (rows wx*32.., 64 e-cols) ---
        uint32_t vfr0[4][4], vfr1[4][4];
        const uint32_t vhb = sb + O_B + buf * BUFB + TBYTES
                           + (uint32_t)(wx * 32 * STR * 2);
        #pragma unroll
        for (int ep = 0; ep < 4; ++ep)
            ldsm4t(vfr0[ep], vhb + A_off + (uint32_t)(ep * 32));

        // --- S[16x32] = Qs @ Kn^T (1-term, Q from registers) ---
        float sc[4][4] = {};
        const uint32_t khb = sb + O_B + buf * BUFB + (uint32_t)(wx * 32 * STR * 2);
        #pragma unroll
        for (int k = 0; k < 4; ++k) {
            uint32_t bh[4];
            uint32_t kcol = (uint32_t)(k * 32);
            #pragma unroll
            for (int np = 0; np < 2; ++np) {
                ldsm4(bh, khb + B_off + (uint32_t)(np * 16 * STR * 2) + kcol);
                mma_f16(sc[2 * np],     aqf[k], bh[0], bh[1]);
                mma_f16(sc[2 * np + 1], aqf[k], bh[2], bh[3]);
            }
        }
        #pragma unroll
        for (int ep = 0; ep < 4; ++ep)
            ldsm4t(vfr1[ep], vhb + A_off + (uint32_t)(16 * STR * 2) + (uint32_t)(ep * 32));

        // --- exp2(s - shp) [pre-normalized] + attn store + fp16 repack ---
        uint32_t ah_[2][4];
        const int gjb = ct * 64 + wx * 32 + 2 * t;
        if (ct != rt) {
            #pragma unroll
            for (int nb = 0; nb < 4; ++nb) {
                int gj = gjb + nb * 8;
                float p00 = exp2f(sc[nb][0] - shp0);
                float p01 = exp2f(sc[nb][1] - shp0);
                float p10 = exp2f(sc[nb][2] - shp1);
                float p11 = exp2f(sc[nb][3] - shp1);
                *(float2*)(arow0 + gj) = make_float2(p00, p01);
                *(float2*)(arow1 + gj) = make_float2(p10, p11);
                int kb = nb >> 1, o = (nb & 1) * 2;
                ah_[kb][o]     = h2u(__floats2half2_rn(p00, p01));
                ah_[kb][o + 1] = h2u(__floats2half2_rn(p10, p11));
            }
        } else {
            #pragma unroll
            for (int nb = 0; nb < 4; ++nb) {
                int gj = gjb + nb * 8;
                float p00 = (gj < gi0)     ? exp2f(sc[nb][0] - shp0) : 0.f;
                float p01 = (gj + 1 < gi0) ? exp2f(sc[nb][1] - shp0) : 0.f;
                float p10 = (gj < gi1)     ? exp2f(sc[nb][2] - shp1) : 0.f;
                float p11 = (gj + 1 < gi1) ? exp2f(sc[nb][3] - shp1) : 0.f;
                *(float2*)(arow0 + gj) = make_float2(p00, p01);
                *(float2*)(arow1 + gj) = make_float2(p10, p11);
                int kb = nb >> 1, o = (nb & 1) * 2;
                ah_[kb][o]     = h2u(__floats2half2_rn(p00, p01));
                ah_[kb][o + 1] = h2u(__floats2half2_rn(p10, p11));
            }
        }

        // --- O += P_norm @ V ---
        #pragma unroll
        for (int ep = 0; ep < 4; ++ep) {
            mma_f16(oc[2 * ep],     ah_[0], vfr0[ep][0], vfr0[ep][1]);
            mma_f16(oc[2 * ep + 1], ah_[0], vfr0[ep][2], vfr0[ep][3]);
            mma_f16(oc[2 * ep],     ah_[1], vfr1[ep][0], vfr1[ep][1]);
            mma_f16(oc[2 * ep + 1], ah_[1], vfr1[ep][2], vfr1[ep][3]);
        }
    }
    __syncthreads();   // all loop reads done (KV region free for obuf)

    // ---- combine column-half O partials via padded smem buffer ----
    float* obuf = (float*)(smc + O_B);   // 64 x 66 floats
    if (wx == 1) {
        #pragma unroll
        for (int nb = 0; nb < 8; ++nb) {
            int c = nb * 8 + 2 * t;
            obuf[r0 * 66 + c]           = oc[nb][0];
            obuf[r0 * 66 + c + 1]       = oc[nb][1];
            obuf[(r0 + 8) * 66 + c]     = oc[nb][2];
            obuf[(r0 + 8) * 66 + c + 1] = oc[nb][3];
        }
    }
    __syncthreads();
    if (wx == 0) {
        float* o0 = out + (bS + gi0) * ND;
        float* o1 = out + (bS + gi1) * ND;
        if (gi0 == 0) {
            const float* vr = v + bS * ND;  // row 0: softmax over single -50000 diag
            #pragma unroll
            for (int nb = 0; nb < 8; ++nb) {
                int c = nb * 8 + 2 * t;
                *(float2*)(o0 + c) = *(const float2*)(vr + c);
            }
        } else {
            #pragma unroll
            for (int nb = 0; nb < 8; ++nb) {
                int c = nb * 8 + 2 * t;
                *(float2*)(o0 + c) = make_float2(oc[nb][0] + obuf[r0 * 66 + c],
                                                 oc[nb][1] + obuf[r0 * 66 + c + 1]);
            }
        }
        #pragma unroll
        for (int nb = 0; nb < 8; ++nb) {
            int c = nb * 8 + 2 * t;
            *(float2*)(o1 + c) = make_float2(oc[nb][2] + obuf[(r0 + 8) * 66 + c],
                                             oc[nb][3] + obuf[(r0 + 8) * 66 + c + 1]);
        }
    }

    // ---- upper-triangle zero-fill (anti-correlated with compute) ----
    {
        int r = tid >> 2;
        float* rowp = attn_b + (size_t)(rt * 64 + r) * NS;
        float4 z = make_float4(0.f, 0.f, 0.f, 0.f);
        for (int c = nt * 64 + (tid & 3) * 4; c < NS; c += 16)
            *(float4*)(rowp + c) = z;
    }
    if (rt == 0 && tid == 0) attn_b[0] = 1.0f;  // row 0: softmax over single diag entry
}

// ---------------------------------------------------------------------------
extern "C" void kernel_launch(void* const* d_in, const int* in_sizes, int n_in,
                              void* d_out, int out_size) {
    const float* qk = (const float*)d_in[0];
    const float* v  = (const float*)d_in[1];
    float* out  = (float*)d_out;
    float* attn = out + (size_t)NB * NS * ND;

    cudaFuncSetAttribute(attn_main, cudaFuncAttributeMaxDynamicSharedMemorySize, SMEM_SZ);
    prep_kernel<<<NB * NS / 8, 256>>>(qk, v);
    attn_main<<<256, 256, SMEM_SZ>>>(v, out, attn);
}